// round 12
// baseline (speedup 1.0000x reference)
#include <cuda_runtime.h>
#include <cuda_bf16.h>
#include <math.h>
#include <stdint.h>

#define NKEYS 131072
#define DDIM 128
#define QDIM 512
#define KTOT 256
#define MAXQ 262144
#define SIGN_TH 5e-4f

__device__ __nv_bfloat16 g_Bh[(size_t)NKEYS * DDIM];   // vn*x_mse hi
__device__ __nv_bfloat16 g_Bl[(size_t)NKEYS * DDIM];   // vn*x_mse lo
__device__ __nv_bfloat16 g_Sg[(size_t)NKEYS * DDIM];   // signs (+-1, exact)
__device__ __nv_bfloat16 g_Rh[(size_t)NKEYS * DDIM];
__device__ __nv_bfloat16 g_Rl[(size_t)NKEYS * DDIM];
__device__ float         g_C [(size_t)NKEYS];
__device__ float         g_Rn[(size_t)NKEYS];
__device__ __nv_bfloat16 g_Sh[DDIM * DDIM];
__device__ __nv_bfloat16 g_Sl[DDIM * DDIM];
__device__ __nv_bfloat16 g_Ah[(size_t)QDIM * KTOT];    // [q | Sq] hi
__device__ __nv_bfloat16 g_Al[(size_t)QDIM * KTOT];    // [q | Sq] lo
__device__ int           g_qcount;
__device__ uint32_t      g_queue[MAXQ];

__device__ __forceinline__ uint32_t smem_u32(const void* p) {
    uint32_t a;
    asm("{ .reg .u64 t; cvta.to.shared.u64 t, %1; cvt.u32.u64 %0, t; }" : "=r"(a) : "l"(p));
    return a;
}
__device__ __forceinline__ void cp_async16(uint32_t dst, const void* src) {
    uint64_t g;
    asm("cvta.to.global.u64 %0, %1;" : "=l"(g) : "l"(src));
    asm volatile("cp.async.cg.shared.global [%0], [%1], 16;" :: "r"(dst), "l"(g));
}
#define CP_COMMIT() asm volatile("cp.async.commit_group;" ::: "memory")
#define CP_WAIT1()  asm volatile("cp.async.wait_group 1;" ::: "memory")
#define CP_WAIT0()  asm volatile("cp.async.wait_group 0;" ::: "memory")

__device__ __forceinline__ void ldsm4(uint32_t& r0, uint32_t& r1, uint32_t& r2,
                                      uint32_t& r3, uint32_t addr) {
    asm volatile("ldmatrix.sync.aligned.m8n8.x4.shared.b16 {%0,%1,%2,%3}, [%4];"
                 : "=r"(r0), "=r"(r1), "=r"(r2), "=r"(r3) : "r"(addr));
}
__device__ __forceinline__ void mma16816(float* c, uint32_t a0, uint32_t a1,
                                         uint32_t a2, uint32_t a3,
                                         uint32_t b0, uint32_t b1) {
    asm volatile(
        "mma.sync.aligned.m16n8k16.row.col.f32.bf16.bf16.f32 "
        "{%0,%1,%2,%3}, {%4,%5,%6,%7}, {%8,%9}, {%0,%1,%2,%3};"
        : "+f"(c[0]), "+f"(c[1]), "+f"(c[2]), "+f"(c[3])
        : "r"(a0), "r"(a1), "r"(a2), "r"(a3), "r"(b0), "r"(b1));
}
__device__ __forceinline__ void bf16split(float v, __nv_bfloat16& h, __nv_bfloat16& l) {
    h = __float2bfloat16(v);
    l = __float2bfloat16(v - __bfloat162float(h));
}
__device__ __forceinline__ uint32_t pack2(__nv_bfloat16 a, __nv_bfloat16 b) {
    union { __nv_bfloat16 h[2]; uint32_t u; } t;
    t.h[0] = a; t.h[1] = b;
    return t.u;
}
__device__ __forceinline__ void enqueue(uint32_t n, uint32_t j) {
    uint32_t idx = (uint32_t)atomicAdd(&g_qcount, 1);
    if (idx < MAXQ) g_queue[idx] = (n << 7) | j;
}

__global__ void zeroq_kernel() { if (threadIdx.x == 0) g_qcount = 0; }

__global__ void build_S_kernel(const float* __restrict__ S) {
    int i = blockIdx.x * 256 + threadIdx.x;
    __nv_bfloat16 h, l;
    bf16split(S[i], h, l);
    g_Sh[i] = h; g_Sl[i] = l;
}

// --- A = [query | query @ S^T] -> bf16 hi/lo ---
__global__ __launch_bounds__(256) void build_A_kernel(const float* __restrict__ query,
                                                      const float* __restrict__ S) {
    extern __shared__ float sh[];
    float* St = sh;
    float* qsh = sh + 128 * 129;
    int t = threadIdx.x, j = t & 127, qs = t >> 7;
    for (int idx = t; idx < 128 * 128; idx += 256) {
        int jj = idx >> 7, ii = idx & 127;
        St[ii * 129 + jj] = S[idx];
    }
    __syncthreads();
    int q0 = blockIdx.x * 8;
    for (int qq = 0; qq < 4; qq++) {
        int q = q0 + qq * 2 + qs;
        float qv = query[q * DDIM + j];
        qsh[qs * 128 + j] = qv;
        __syncthreads();
        float acc = 0.f;
#pragma unroll 8
        for (int i = 0; i < 128; i++) acc += qsh[qs * 128 + i] * St[i * 129 + j];
        __nv_bfloat16 h, l;
        bf16split(qv, h, l);
        g_Ah[(size_t)q * KTOT + j] = h; g_Al[(size_t)q * KTOT + j] = l;
        bf16split(acc, h, l);
        g_Ah[(size_t)q * KTOT + 128 + j] = h; g_Al[(size_t)q * KTOT + 128 + j] = l;
        __syncthreads();
    }
}

// --- prep1: warp-per-key ---
__global__ __launch_bounds__(256) void prep1_kernel(const float* __restrict__ keys,
                                                    const float* __restrict__ cb) {
    int lane = threadIdx.x & 31, w = threadIdx.x >> 5;
    size_t n = (size_t)blockIdx.x * 8 + w;
    float c0 = cb[0], c1 = cb[1], c2 = cb[2], c3 = cb[3];
    float m01 = 0.5f * (c0 + c1), m12 = 0.5f * (c1 + c2), m23 = 0.5f * (c2 + c3);

    float4 kv = *(const float4*)(keys + n * DDIM + lane * 4);
    float ss = kv.x * kv.x + kv.y * kv.y + kv.z * kv.z + kv.w * kv.w;
#pragma unroll
    for (int o = 16; o; o >>= 1) ss += __shfl_xor_sync(0xffffffffu, ss, o);
    float vn = sqrtf(ss);
    float inv = 1.f / (vn + 1e-8f);

    float x[4] = {kv.x * inv, kv.y * inv, kv.z * inv, kv.w * inv};
    float r[4], rr = 0.f;
    __nv_bfloat16 th[4], tl[4];
#pragma unroll
    for (int i = 0; i < 4; i++) {
        float xm = (x[i] >= m12) ? ((x[i] >= m23) ? c3 : c2)
                                 : ((x[i] >= m01) ? c1 : c0);
        r[i] = x[i] - xm;
        rr += r[i] * r[i];
        bf16split(vn * xm, th[i], tl[i]);
    }
    *(uint2*)&g_Bh[n * DDIM + lane * 4] = make_uint2(pack2(th[0], th[1]), pack2(th[2], th[3]));
    *(uint2*)&g_Bl[n * DDIM + lane * 4] = make_uint2(pack2(tl[0], tl[1]), pack2(tl[2], tl[3]));

#pragma unroll
    for (int o = 16; o; o >>= 1) rr += __shfl_xor_sync(0xffffffffu, rr, o);
    float rn = sqrtf(rr);

    __nv_bfloat16 rh[4], rl[4];
#pragma unroll
    for (int i = 0; i < 4; i++) bf16split(r[i], rh[i], rl[i]);
    *(uint2*)&g_Rh[n * DDIM + lane * 4] = make_uint2(pack2(rh[0], rh[1]), pack2(rh[2], rh[3]));
    *(uint2*)&g_Rl[n * DDIM + lane * 4] = make_uint2(pack2(rl[0], rl[1]), pack2(rl[2], rl[3]));
    if (lane == 0) {
        g_C[n]  = vn * rn * 0.009797554543986288f;  // sqrt(pi/2)/128
        g_Rn[n] = rn;
    }
}

// --- proj: sign(R @ S^T) -> g_Sg (+-1); enqueue ambiguous signs ---
#define PROW 272
#define PARR 34816

__global__ __launch_bounds__(256, 1) void proj_kernel() {
    extern __shared__ __align__(16) char sm[];
    uint32_t sb = smem_u32(sm);
    int tid = threadIdx.x, wid = tid >> 5, lane = tid & 31;
    int wm = wid >> 2, wn = wid & 3;
    size_t n0 = (size_t)blockIdx.x * 128;

#pragma unroll
    for (int it = 0; it < 8; it++) {
        int idx = tid + it * 256;
        int row = idx >> 4, c16 = idx & 15;
        uint32_t d = (uint32_t)(row * PROW + c16 * 16);
        size_t ro = (n0 + (size_t)row) * DDIM + c16 * 8;
        cp_async16(sb + d,            g_Rh + ro);
        cp_async16(sb + PARR + d,     g_Rl + ro);
        size_t so = (size_t)row * DDIM + c16 * 8;
        cp_async16(sb + 2 * PARR + d, g_Sh + so);
        cp_async16(sb + 3 * PARR + d, g_Sl + so);
    }
    CP_COMMIT();

    float acc[4][4][4];
#pragma unroll
    for (int i = 0; i < 4; i++)
#pragma unroll
        for (int j = 0; j < 4; j++)
#pragma unroll
            for (int k = 0; k < 4; k++) acc[i][j][k] = 0.f;

    CP_WAIT0();
    __syncthreads();

    int lr = lane & 15, lc = (lane >> 4) * 8;
#pragma unroll
    for (int ks = 0; ks < 8; ks++) {
        uint32_t coff = (uint32_t)((ks * 16 + lc) * 2);
        uint32_t bh[8], bl[8];
#pragma unroll
        for (int h = 0; h < 2; h++) {
            uint32_t bd = sb + 2 * PARR + (uint32_t)((wn * 32 + h * 16 + lr) * PROW) + coff;
            ldsm4(bh[h * 4 + 0], bh[h * 4 + 1], bh[h * 4 + 2], bh[h * 4 + 3], bd);
            ldsm4(bl[h * 4 + 0], bl[h * 4 + 1], bl[h * 4 + 2], bl[h * 4 + 3], bd + PARR);
        }
#pragma unroll
        for (int mi = 0; mi < 4; mi++) {
            uint32_t ad = sb + (uint32_t)((wm * 64 + mi * 16 + lr) * PROW) + coff;
            uint32_t ah0, ah1, ah2, ah3, al0, al1, al2, al3;
            ldsm4(ah0, ah1, ah2, ah3, ad);
            ldsm4(al0, al1, al2, al3, ad + PARR);
#pragma unroll
            for (int ni = 0; ni < 4; ni++) {
                int h = ni >> 1, s2 = ni & 1;
                uint32_t b0h = bh[h * 4 + s2], b1h = bh[h * 4 + s2 + 2];
                uint32_t b0l = bl[h * 4 + s2], b1l = bl[h * 4 + s2 + 2];
                mma16816(acc[mi][ni], ah0, ah1, ah2, ah3, b0h, b1h);
                mma16816(acc[mi][ni], al0, al1, al2, al3, b0h, b1h);
                mma16816(acc[mi][ni], ah0, ah1, ah2, ah3, b0l, b1l);
            }
        }
    }

    int g = lane >> 2, tc = lane & 3;
    __nv_bfloat16 one = __float2bfloat16(1.f), mone = __float2bfloat16(-1.f);
#pragma unroll
    for (int mi = 0; mi < 4; mi++) {
        size_t r0 = n0 + (size_t)(wm * 64 + mi * 16 + g);
        size_t r1 = r0 + 8;
        float tA = g_Rn[r0] * SIGN_TH, tB = g_Rn[r1] * SIGN_TH;
#pragma unroll
        for (int ni = 0; ni < 4; ni++) {
            int j0 = wn * 32 + ni * 8 + tc * 2;
            bool p0 = acc[mi][ni][0] >= 0.f, p1 = acc[mi][ni][1] >= 0.f;
            bool p2 = acc[mi][ni][2] >= 0.f, p3 = acc[mi][ni][3] >= 0.f;
            *(uint32_t*)&g_Sg[r0 * DDIM + j0] = pack2(p0 ? one : mone, p1 ? one : mone);
            *(uint32_t*)&g_Sg[r1 * DDIM + j0] = pack2(p2 ? one : mone, p3 ? one : mone);
            if (fabsf(acc[mi][ni][0]) < tA) enqueue((uint32_t)r0, (uint32_t)j0);
            if (fabsf(acc[mi][ni][1]) < tA) enqueue((uint32_t)r0, (uint32_t)(j0 + 1));
            if (fabsf(acc[mi][ni][2]) < tB) enqueue((uint32_t)r1, (uint32_t)j0);
            if (fabsf(acc[mi][ni][3]) < tB) enqueue((uint32_t)r1, (uint32_t)(j0 + 1));
        }
    }
}

// --- fixup: recompute ambiguous signs in exact fp32 ---
__global__ __launch_bounds__(256) void fixup_kernel(const float* __restrict__ keys,
                                                    const float* __restrict__ cb,
                                                    const float* __restrict__ S) {
    int lane = threadIdx.x & 31;
    int w = (blockIdx.x * blockDim.x + threadIdx.x) >> 5;
    int nw = (gridDim.x * blockDim.x) >> 5;
    int cnt = g_qcount;
    if (cnt > MAXQ) cnt = MAXQ;
    float c0 = cb[0], c1 = cb[1], c2 = cb[2], c3 = cb[3];
    float m01 = 0.5f * (c0 + c1), m12 = 0.5f * (c1 + c2), m23 = 0.5f * (c2 + c3);

    for (int e = w; e < cnt; e += nw) {
        uint32_t pk = g_queue[e];
        size_t n = (size_t)(pk >> 7);
        uint32_t j = pk & 127u;
        float4 kv = *(const float4*)(keys + n * DDIM + lane * 4);
        float ss = kv.x * kv.x + kv.y * kv.y + kv.z * kv.z + kv.w * kv.w;
#pragma unroll
        for (int o = 16; o; o >>= 1) ss += __shfl_xor_sync(0xffffffffu, ss, o);
        float vn = sqrtf(ss);
        float inv = 1.f / (vn + 1e-8f);
        float x[4] = {kv.x * inv, kv.y * inv, kv.z * inv, kv.w * inv};
        float4 sv = *(const float4*)(S + (size_t)j * DDIM + lane * 4);
        float svv[4] = {sv.x, sv.y, sv.z, sv.w};
        float dot = 0.f;
#pragma unroll
        for (int i = 0; i < 4; i++) {
            float xm = (x[i] >= m12) ? ((x[i] >= m23) ? c3 : c2)
                                     : ((x[i] >= m01) ? c1 : c0);
            dot += (x[i] - xm) * svv[i];
        }
#pragma unroll
        for (int o = 16; o; o >>= 1) dot += __shfl_xor_sync(0xffffffffu, dot, o);
        if (lane == 0)
            g_Sg[n * DDIM + j] = __float2bfloat16((dot >= 0.f) ? 1.f : -1.f);
    }
}

// --- main GEMM: dual-accumulator, 5 K=128 passes.
//     phase1 (kc 0..3): acc1 += q @ (vn*xm)^T  (3-term split)
//     phase2 (kc 4..7): acc2 += Sq @ sign^T    (2 terms, signs exact)
//     epilogue: out = acc1 + coef_n * acc2
#define ROWB 80
#define ARR  10240
#define STG  40960

__global__ __launch_bounds__(256, 1) void gemm_kernel(float* __restrict__ out) {
    extern __shared__ __align__(16) char sm[];
    __shared__ float sC[128];
    uint32_t sb = smem_u32(sm);
    int tid = threadIdx.x, wid = tid >> 5, lane = tid & 31;
    int wm = wid >> 2, wn = wid & 3;
    size_t q0 = (size_t)blockIdx.x * 128;
    size_t n0 = (size_t)blockIdx.y * 128;
    if (tid < 128) sC[tid] = g_C[n0 + tid];

    float acc1[4][4][4], acc2[4][4][4];
#pragma unroll
    for (int i = 0; i < 4; i++)
#pragma unroll
        for (int j = 0; j < 4; j++)
#pragma unroll
            for (int k = 0; k < 4; k++) { acc1[i][j][k] = 0.f; acc2[i][j][k] = 0.f; }

#define LOAD_CHUNK(CC, S_)                                                    \
    do {                                                                      \
        uint32_t stg_ = sb + (S_) * STG;                                      \
        int cc_ = (CC);                                                       \
        if (cc_ < 4) {                                                        \
            int kofs_ = cc_ * 32;                                             \
            _Pragma("unroll")                                                 \
            for (int it = 0; it < 2; it++) {                                  \
                int idx = tid + it * 256;                                     \
                int row = idx >> 2, c16 = idx & 3;                            \
                uint32_t d = (uint32_t)(row * ROWB + c16 * 16);               \
                size_t ao = (q0 + (size_t)row) * KTOT + kofs_ + c16 * 8;      \
                cp_async16(stg_ + d,           g_Ah + ao);                    \
                cp_async16(stg_ + ARR + d,     g_Al + ao);                    \
                size_t bo = (n0 + (size_t)row) * DDIM + kofs_ + c16 * 8;      \
                cp_async16(stg_ + 2 * ARR + d, g_Bh + bo);                    \
                cp_async16(stg_ + 3 * ARR + d, g_Bl + bo);                    \
            }                                                                 \
        } else {                                                              \
            int kofs_ = (cc_ - 4) * 32;                                       \
            _Pragma("unroll")                                                 \
            for (int it = 0; it < 2; it++) {                                  \
                int idx = tid + it * 256;                                     \
                int row = idx >> 2, c16 = idx & 3;                            \
                uint32_t d = (uint32_t)(row * ROWB + c16 * 16);               \
                size_t ao = (q0 + (size_t)row) * KTOT + 128 + kofs_ + c16 * 8;\
                cp_async16(stg_ + d,           g_Ah + ao);                    \
                cp_async16(stg_ + ARR + d,     g_Al + ao);                    \
                size_t bo = (n0 + (size_t)row) * DDIM + kofs_ + c16 * 8;      \
                cp_async16(stg_ + 2 * ARR + d, g_Sg + bo);                    \
            }                                                                 \
        }                                                                     \
        CP_COMMIT();                                                          \
    } while (0)

    LOAD_CHUNK(0, 0);
    int lr = lane & 15, lc = (lane >> 4) * 8;

    for (int kc = 0; kc < 8; kc++) {
        if (kc < 7) { LOAD_CHUNK(kc + 1, (kc + 1) & 1); CP_WAIT1(); }
        else        { CP_WAIT0(); }
        __syncthreads();
        uint32_t stg = sb + (kc & 1) * STG;
        if (kc < 4) {
#pragma unroll
            for (int ks = 0; ks < 2; ks++) {
                uint32_t coff = (uint32_t)((ks * 16 + lc) * 2);
                uint32_t bh[8], bl[8];
#pragma unroll
                for (int h = 0; h < 2; h++) {
                    uint32_t bd = stg + 2 * ARR + (uint32_t)((wn * 32 + h * 16 + lr) * ROWB) + coff;
                    ldsm4(bh[h * 4 + 0], bh[h * 4 + 1], bh[h * 4 + 2], bh[h * 4 + 3], bd);
                    ldsm4(bl[h * 4 + 0], bl[h * 4 + 1], bl[h * 4 + 2], bl[h * 4 + 3], bd + ARR);
                }
#pragma unroll
                for (int mi = 0; mi < 4; mi++) {
                    uint32_t ad = stg + (uint32_t)((wm * 64 + mi * 16 + lr) * ROWB) + coff;
                    uint32_t ah0, ah1, ah2, ah3, al0, al1, al2, al3;
                    ldsm4(ah0, ah1, ah2, ah3, ad);
                    ldsm4(al0, al1, al2, al3, ad + ARR);
#pragma unroll
                    for (int ni = 0; ni < 4; ni++) {
                        int h = ni >> 1, s2 = ni & 1;
                        uint32_t b0h = bh[h * 4 + s2], b1h = bh[h * 4 + s2 + 2];
                        uint32_t b0l = bl[h * 4 + s2], b1l = bl[h * 4 + s2 + 2];
                        mma16816(acc1[mi][ni], ah0, ah1, ah2, ah3, b0h, b1h);
                        mma16816(acc1[mi][ni], al0, al1, al2, al3, b0h, b1h);
                        mma16816(acc1[mi][ni], ah0, ah1, ah2, ah3, b0l, b1l);
                    }
                }
            }
        } else {
#pragma unroll
            for (int ks = 0; ks < 2; ks++) {
                uint32_t coff = (uint32_t)((ks * 16 + lc) * 2);
                uint32_t bg[8];
#pragma unroll
                for (int h = 0; h < 2; h++) {
                    uint32_t bd = stg + 2 * ARR + (uint32_t)((wn * 32 + h * 16 + lr) * ROWB) + coff;
                    ldsm4(bg[h * 4 + 0], bg[h * 4 + 1], bg[h * 4 + 2], bg[h * 4 + 3], bd);
                }
#pragma unroll
                for (int mi = 0; mi < 4; mi++) {
                    uint32_t ad = stg + (uint32_t)((wm * 64 + mi * 16 + lr) * ROWB) + coff;
                    uint32_t ah0, ah1, ah2, ah3, al0, al1, al2, al3;
                    ldsm4(ah0, ah1, ah2, ah3, ad);
                    ldsm4(al0, al1, al2, al3, ad + ARR);
#pragma unroll
                    for (int ni = 0; ni < 4; ni++) {
                        int h = ni >> 1, s2 = ni & 1;
                        uint32_t b0 = bg[h * 4 + s2], b1 = bg[h * 4 + s2 + 2];
                        mma16816(acc2[mi][ni], ah0, ah1, ah2, ah3, b0, b1);
                        mma16816(acc2[mi][ni], al0, al1, al2, al3, b0, b1);
                    }
                }
            }
        }
        __syncthreads();
    }

    int g = lane >> 2, tc = lane & 3;
#pragma unroll
    for (int mi = 0; mi < 4; mi++) {
        size_t r0 = q0 + (size_t)(wm * 64 + mi * 16 + g);
        size_t r1 = r0 + 8;
#pragma unroll
        for (int ni = 0; ni < 4; ni++) {
            int lc0 = wn * 32 + ni * 8 + tc * 2;
            float cc0 = sC[lc0], cc1 = sC[lc0 + 1];
            size_t col = n0 + (size_t)lc0;
            *(float2*)(out + r0 * NKEYS + col) =
                make_float2(acc1[mi][ni][0] + cc0 * acc2[mi][ni][0],
                            acc1[mi][ni][1] + cc1 * acc2[mi][ni][1]);
            *(float2*)(out + r1 * NKEYS + col) =
                make_float2(acc1[mi][ni][2] + cc0 * acc2[mi][ni][2],
                            acc1[mi][ni][3] + cc1 * acc2[mi][ni][3]);
        }
    }
}

extern "C" void kernel_launch(void* const* d_in, const int* in_sizes, int n_in,
                              void* d_out, int out_size) {
    const float* query    = (const float*)d_in[0];
    const float* keys     = (const float*)d_in[1];
    const float* codebook = (const float*)d_in[2];
    const float* S        = (const float*)d_in[3];
    float* out = (float*)d_out;

    zeroq_kernel<<<1, 32>>>();
    build_S_kernel<<<64, 256>>>(S);

    int shA = (128 * 129 + 256) * 4;
    cudaFuncSetAttribute(build_A_kernel, cudaFuncAttributeMaxDynamicSharedMemorySize, shA);
    build_A_kernel<<<64, 256, shA>>>(query, S);

    prep1_kernel<<<NKEYS / 8, 256>>>(keys, codebook);

    int shP = 4 * PARR;  // 139264
    cudaFuncSetAttribute(proj_kernel, cudaFuncAttributeMaxDynamicSharedMemorySize, shP);
    proj_kernel<<<NKEYS / 128, 256, shP>>>();

    fixup_kernel<<<256, 256>>>(keys, codebook, S);

    int shG = 2 * STG;   // 81920
    cudaFuncSetAttribute(gemm_kernel, cudaFuncAttributeMaxDynamicSharedMemorySize, shG);
    dim3 grid(QDIM / 128, NKEYS / 128);
    gemm_kernel<<<grid, 256, shG>>>(out);
}

// round 13
// speedup vs baseline: 1.3503x; 1.3503x over previous
#include <cuda_runtime.h>
#include <cuda_bf16.h>
#include <cuda_fp16.h>
#include <math.h>
#include <stdint.h>

#define NKEYS 131072
#define DDIM 128
#define QDIM 512
#define KTOT 256
#define MAXQ 262144
#define SIGN_TH 5e-4f

__device__ __half        g_B [(size_t)NKEYS * KTOT];   // [vn*x_mse | coef*sign] fp16
__device__ __nv_bfloat16 g_Rh[(size_t)NKEYS * DDIM];
__device__ __nv_bfloat16 g_Rl[(size_t)NKEYS * DDIM];
__device__ float         g_C [(size_t)NKEYS];
__device__ float         g_Rn[(size_t)NKEYS];
__device__ __nv_bfloat16 g_Sh[DDIM * DDIM];
__device__ __nv_bfloat16 g_Sl[DDIM * DDIM];
__device__ __half        g_Ah[(size_t)QDIM * KTOT];    // [q | Sq] fp16 hi
__device__ __half        g_Al[(size_t)QDIM * KTOT];    // [q | Sq] fp16 lo
__device__ int           g_qcount;
__device__ uint32_t      g_queue[MAXQ];

__device__ __forceinline__ uint32_t smem_u32(const void* p) {
    uint32_t a;
    asm("{ .reg .u64 t; cvta.to.shared.u64 t, %1; cvt.u32.u64 %0, t; }" : "=r"(a) : "l"(p));
    return a;
}
__device__ __forceinline__ void cp_async16(uint32_t dst, const void* src) {
    uint64_t g;
    asm("cvta.to.global.u64 %0, %1;" : "=l"(g) : "l"(src));
    asm volatile("cp.async.cg.shared.global [%0], [%1], 16;" :: "r"(dst), "l"(g));
}
#define CP_COMMIT() asm volatile("cp.async.commit_group;" ::: "memory")
#define CP_WAIT1()  asm volatile("cp.async.wait_group 1;" ::: "memory")
#define CP_WAIT0()  asm volatile("cp.async.wait_group 0;" ::: "memory")

__device__ __forceinline__ void ldsm4(uint32_t& r0, uint32_t& r1, uint32_t& r2,
                                      uint32_t& r3, uint32_t addr) {
    asm volatile("ldmatrix.sync.aligned.m8n8.x4.shared.b16 {%0,%1,%2,%3}, [%4];"
                 : "=r"(r0), "=r"(r1), "=r"(r2), "=r"(r3) : "r"(addr));
}
__device__ __forceinline__ void mma_bf(float* c, uint32_t a0, uint32_t a1,
                                       uint32_t a2, uint32_t a3,
                                       uint32_t b0, uint32_t b1) {
    asm volatile(
        "mma.sync.aligned.m16n8k16.row.col.f32.bf16.bf16.f32 "
        "{%0,%1,%2,%3}, {%4,%5,%6,%7}, {%8,%9}, {%0,%1,%2,%3};"
        : "+f"(c[0]), "+f"(c[1]), "+f"(c[2]), "+f"(c[3])
        : "r"(a0), "r"(a1), "r"(a2), "r"(a3), "r"(b0), "r"(b1));
}
__device__ __forceinline__ void mma_fp(float* c, uint32_t a0, uint32_t a1,
                                       uint32_t a2, uint32_t a3,
                                       uint32_t b0, uint32_t b1) {
    asm volatile(
        "mma.sync.aligned.m16n8k16.row.col.f32.f16.f16.f32 "
        "{%0,%1,%2,%3}, {%4,%5,%6,%7}, {%8,%9}, {%0,%1,%2,%3};"
        : "+f"(c[0]), "+f"(c[1]), "+f"(c[2]), "+f"(c[3])
        : "r"(a0), "r"(a1), "r"(a2), "r"(a3), "r"(b0), "r"(b1));
}
__device__ __forceinline__ void bf16split(float v, __nv_bfloat16& h, __nv_bfloat16& l) {
    h = __float2bfloat16(v);
    l = __float2bfloat16(v - __bfloat162float(h));
}
__device__ __forceinline__ void fp16split(float v, __half& h, __half& l) {
    h = __float2half(v);
    l = __float2half(v - __half2float(h));
}
__device__ __forceinline__ uint32_t pack2b(__nv_bfloat16 a, __nv_bfloat16 b) {
    union { __nv_bfloat16 h[2]; uint32_t u; } t;
    t.h[0] = a; t.h[1] = b;
    return t.u;
}
__device__ __forceinline__ uint32_t pack2h(__half a, __half b) {
    union { __half h[2]; uint32_t u; } t;
    t.h[0] = a; t.h[1] = b;
    return t.u;
}
__device__ __forceinline__ void enqueue(uint32_t n, uint32_t j) {
    uint32_t idx = (uint32_t)atomicAdd(&g_qcount, 1);
    if (idx < MAXQ) g_queue[idx] = (n << 7) | j;
}

__global__ void zeroq_kernel() { if (threadIdx.x == 0) g_qcount = 0; }

__global__ void build_S_kernel(const float* __restrict__ S) {
    int i = blockIdx.x * 256 + threadIdx.x;
    __nv_bfloat16 h, l;
    bf16split(S[i], h, l);
    g_Sh[i] = h; g_Sl[i] = l;
}

// --- A = [query | query @ S^T] -> fp16 hi/lo ---
__global__ __launch_bounds__(256) void build_A_kernel(const float* __restrict__ query,
                                                      const float* __restrict__ S) {
    extern __shared__ float sh[];
    float* St = sh;
    float* qsh = sh + 128 * 129;
    int t = threadIdx.x, j = t & 127, qs = t >> 7;
    for (int idx = t; idx < 128 * 128; idx += 256) {
        int jj = idx >> 7, ii = idx & 127;
        St[ii * 129 + jj] = S[idx];
    }
    __syncthreads();
    int q0 = blockIdx.x * 8;
    for (int qq = 0; qq < 4; qq++) {
        int q = q0 + qq * 2 + qs;
        float qv = query[q * DDIM + j];
        qsh[qs * 128 + j] = qv;
        __syncthreads();
        float acc = 0.f;
#pragma unroll 8
        for (int i = 0; i < 128; i++) acc += qsh[qs * 128 + i] * St[i * 129 + j];
        __half h, l;
        fp16split(qv, h, l);
        g_Ah[(size_t)q * KTOT + j] = h; g_Al[(size_t)q * KTOT + j] = l;
        fp16split(acc, h, l);
        g_Ah[(size_t)q * KTOT + 128 + j] = h; g_Al[(size_t)q * KTOT + 128 + j] = l;
        __syncthreads();
    }
}

// --- prep1: warp-per-key ---
__global__ __launch_bounds__(256) void prep1_kernel(const float* __restrict__ keys,
                                                    const float* __restrict__ cb) {
    int lane = threadIdx.x & 31, w = threadIdx.x >> 5;
    size_t n = (size_t)blockIdx.x * 8 + w;
    float c0 = cb[0], c1 = cb[1], c2 = cb[2], c3 = cb[3];
    float m01 = 0.5f * (c0 + c1), m12 = 0.5f * (c1 + c2), m23 = 0.5f * (c2 + c3);

    float4 kv = *(const float4*)(keys + n * DDIM + lane * 4);
    float ss = kv.x * kv.x + kv.y * kv.y + kv.z * kv.z + kv.w * kv.w;
#pragma unroll
    for (int o = 16; o; o >>= 1) ss += __shfl_xor_sync(0xffffffffu, ss, o);
    float vn = sqrtf(ss);
    float inv = 1.f / (vn + 1e-8f);

    float x[4] = {kv.x * inv, kv.y * inv, kv.z * inv, kv.w * inv};
    float r[4], rr = 0.f;
    __half bq[4];
#pragma unroll
    for (int i = 0; i < 4; i++) {
        float xm = (x[i] >= m12) ? ((x[i] >= m23) ? c3 : c2)
                                 : ((x[i] >= m01) ? c1 : c0);
        r[i] = x[i] - xm;
        rr += r[i] * r[i];
        bq[i] = __float2half(vn * xm);
    }
    *(uint2*)&g_B[n * KTOT + lane * 4] = make_uint2(pack2h(bq[0], bq[1]), pack2h(bq[2], bq[3]));

#pragma unroll
    for (int o = 16; o; o >>= 1) rr += __shfl_xor_sync(0xffffffffu, rr, o);
    float rn = sqrtf(rr);

    __nv_bfloat16 rh[4], rl[4];
#pragma unroll
    for (int i = 0; i < 4; i++) bf16split(r[i], rh[i], rl[i]);
    *(uint2*)&g_Rh[n * DDIM + lane * 4] = make_uint2(pack2b(rh[0], rh[1]), pack2b(rh[2], rh[3]));
    *(uint2*)&g_Rl[n * DDIM + lane * 4] = make_uint2(pack2b(rl[0], rl[1]), pack2b(rl[2], rl[3]));
    if (lane == 0) {
        g_C[n]  = vn * rn * 0.009797554543986288f;  // sqrt(pi/2)/128
        g_Rn[n] = rn;
    }
}

// --- proj: sign(R @ S^T)*coef -> g_B[:,128:256] (fp16); enqueue ambiguous ---
#define PROW 272
#define PARR 34816

__global__ __launch_bounds__(256, 1) void proj_kernel() {
    extern __shared__ __align__(16) char sm[];
    uint32_t sb = smem_u32(sm);
    int tid = threadIdx.x, wid = tid >> 5, lane = tid & 31;
    int wm = wid >> 2, wn = wid & 3;
    size_t n0 = (size_t)blockIdx.x * 128;

#pragma unroll
    for (int it = 0; it < 8; it++) {
        int idx = tid + it * 256;
        int row = idx >> 4, c16 = idx & 15;
        uint32_t d = (uint32_t)(row * PROW + c16 * 16);
        size_t ro = (n0 + (size_t)row) * DDIM + c16 * 8;
        cp_async16(sb + d,            g_Rh + ro);
        cp_async16(sb + PARR + d,     g_Rl + ro);
        size_t so = (size_t)row * DDIM + c16 * 8;
        cp_async16(sb + 2 * PARR + d, g_Sh + so);
        cp_async16(sb + 3 * PARR + d, g_Sl + so);
    }
    CP_COMMIT();

    float acc[4][4][4];
#pragma unroll
    for (int i = 0; i < 4; i++)
#pragma unroll
        for (int j = 0; j < 4; j++)
#pragma unroll
            for (int k = 0; k < 4; k++) acc[i][j][k] = 0.f;

    CP_WAIT0();
    __syncthreads();

    int lr = lane & 15, lc = (lane >> 4) * 8;
#pragma unroll
    for (int ks = 0; ks < 8; ks++) {
        uint32_t coff = (uint32_t)((ks * 16 + lc) * 2);
        uint32_t bh[8], bl[8];
#pragma unroll
        for (int h = 0; h < 2; h++) {
            uint32_t bd = sb + 2 * PARR + (uint32_t)((wn * 32 + h * 16 + lr) * PROW) + coff;
            ldsm4(bh[h * 4 + 0], bh[h * 4 + 1], bh[h * 4 + 2], bh[h * 4 + 3], bd);
            ldsm4(bl[h * 4 + 0], bl[h * 4 + 1], bl[h * 4 + 2], bl[h * 4 + 3], bd + PARR);
        }
#pragma unroll
        for (int mi = 0; mi < 4; mi++) {
            uint32_t ad = sb + (uint32_t)((wm * 64 + mi * 16 + lr) * PROW) + coff;
            uint32_t ah0, ah1, ah2, ah3, al0, al1, al2, al3;
            ldsm4(ah0, ah1, ah2, ah3, ad);
            ldsm4(al0, al1, al2, al3, ad + PARR);
#pragma unroll
            for (int ni = 0; ni < 4; ni++) {
                int h = ni >> 1, s2 = ni & 1;
                uint32_t b0h = bh[h * 4 + s2], b1h = bh[h * 4 + s2 + 2];
                uint32_t b0l = bl[h * 4 + s2], b1l = bl[h * 4 + s2 + 2];
                mma_bf(acc[mi][ni], ah0, ah1, ah2, ah3, b0h, b1h);
                mma_bf(acc[mi][ni], al0, al1, al2, al3, b0h, b1h);
                mma_bf(acc[mi][ni], ah0, ah1, ah2, ah3, b0l, b1l);
            }
        }
    }

    int g = lane >> 2, tc = lane & 3;
#pragma unroll
    for (int mi = 0; mi < 4; mi++) {
        size_t r0 = n0 + (size_t)(wm * 64 + mi * 16 + g);
        size_t r1 = r0 + 8;
        float tA = g_Rn[r0] * SIGN_TH, tB = g_Rn[r1] * SIGN_TH;
        __half cA = __float2half(g_C[r0]), cB = __float2half(g_C[r1]);
#pragma unroll
        for (int ni = 0; ni < 4; ni++) {
            int j0 = wn * 32 + ni * 8 + tc * 2;
            bool p0 = acc[mi][ni][0] >= 0.f, p1 = acc[mi][ni][1] >= 0.f;
            bool p2 = acc[mi][ni][2] >= 0.f, p3 = acc[mi][ni][3] >= 0.f;
            *(uint32_t*)&g_B[r0 * KTOT + 128 + j0] =
                pack2h(p0 ? cA : __hneg(cA), p1 ? cA : __hneg(cA));
            *(uint32_t*)&g_B[r1 * KTOT + 128 + j0] =
                pack2h(p2 ? cB : __hneg(cB), p3 ? cB : __hneg(cB));
            if (fabsf(acc[mi][ni][0]) < tA) enqueue((uint32_t)r0, (uint32_t)j0);
            if (fabsf(acc[mi][ni][1]) < tA) enqueue((uint32_t)r0, (uint32_t)(j0 + 1));
            if (fabsf(acc[mi][ni][2]) < tB) enqueue((uint32_t)r1, (uint32_t)j0);
            if (fabsf(acc[mi][ni][3]) < tB) enqueue((uint32_t)r1, (uint32_t)(j0 + 1));
        }
    }
}

// --- fixup: recompute ambiguous signs in exact fp32 ---
__global__ __launch_bounds__(256) void fixup_kernel(const float* __restrict__ keys,
                                                    const float* __restrict__ cb,
                                                    const float* __restrict__ S) {
    int lane = threadIdx.x & 31;
    int w = (blockIdx.x * blockDim.x + threadIdx.x) >> 5;
    int nw = (gridDim.x * blockDim.x) >> 5;
    int cnt = g_qcount;
    if (cnt > MAXQ) cnt = MAXQ;
    float c0 = cb[0], c1 = cb[1], c2 = cb[2], c3 = cb[3];
    float m01 = 0.5f * (c0 + c1), m12 = 0.5f * (c1 + c2), m23 = 0.5f * (c2 + c3);

    for (int e = w; e < cnt; e += nw) {
        uint32_t pk = g_queue[e];
        size_t n = (size_t)(pk >> 7);
        uint32_t j = pk & 127u;
        float4 kv = *(const float4*)(keys + n * DDIM + lane * 4);
        float ss = kv.x * kv.x + kv.y * kv.y + kv.z * kv.z + kv.w * kv.w;
#pragma unroll
        for (int o = 16; o; o >>= 1) ss += __shfl_xor_sync(0xffffffffu, ss, o);
        float vn = sqrtf(ss);
        float inv = 1.f / (vn + 1e-8f);
        float x[4] = {kv.x * inv, kv.y * inv, kv.z * inv, kv.w * inv};
        float4 sv = *(const float4*)(S + (size_t)j * DDIM + lane * 4);
        float svv[4] = {sv.x, sv.y, sv.z, sv.w};
        float dot = 0.f;
#pragma unroll
        for (int i = 0; i < 4; i++) {
            float xm = (x[i] >= m12) ? ((x[i] >= m23) ? c3 : c2)
                                     : ((x[i] >= m01) ? c1 : c0);
            dot += (x[i] - xm) * svv[i];
        }
#pragma unroll
        for (int o = 16; o; o >>= 1) dot += __shfl_xor_sync(0xffffffffu, dot, o);
        if (lane == 0) {
            float coef = g_C[n];
            g_B[n * KTOT + 128 + j] = __float2half((dot >= 0.f) ? coef : -coef);
        }
    }
}

// --- main GEMM: fp16, 2 terms (Ah.B + Al.B), K=256, occ 2 ---
#define ROWB 80
#define ARR  10240
#define STG  30720    // 3*ARR

__global__ __launch_bounds__(256, 2) void gemm_kernel(float* __restrict__ out) {
    extern __shared__ __align__(16) char sm[];
    uint32_t sb = smem_u32(sm);
    int tid = threadIdx.x, wid = tid >> 5, lane = tid & 31;
    int wm = wid >> 2, wn = wid & 3;
    size_t q0 = (size_t)blockIdx.x * 128;
    size_t n0 = (size_t)blockIdx.y * 128;

    float acc[4][4][4];
#pragma unroll
    for (int i = 0; i < 4; i++)
#pragma unroll
        for (int j = 0; j < 4; j++)
#pragma unroll
            for (int k = 0; k < 4; k++) acc[i][j][k] = 0.f;

#define LOAD_STAGE(KC, S_)                                                    \
    do {                                                                      \
        uint32_t stg_ = sb + (S_) * STG;                                      \
        int kofs_ = (KC) * 32;                                                \
        _Pragma("unroll")                                                     \
        for (int it = 0; it < 2; it++) {                                      \
            int idx = tid + it * 256;                                         \
            int row = idx >> 2, c16 = idx & 3;                                \
            uint32_t d = (uint32_t)(row * ROWB + c16 * 16);                   \
            size_t ao = (q0 + (size_t)row) * KTOT + kofs_ + c16 * 8;          \
            cp_async16(stg_ + d,           g_Ah + ao);                        \
            cp_async16(stg_ + ARR + d,     g_Al + ao);                        \
            size_t bo = (n0 + (size_t)row) * KTOT + kofs_ + c16 * 8;          \
            cp_async16(stg_ + 2 * ARR + d, g_B + bo);                         \
        }                                                                     \
        CP_COMMIT();                                                          \
    } while (0)

    LOAD_STAGE(0, 0);
    int lr = lane & 15, lc = (lane >> 4) * 8;

    for (int kc = 0; kc < 8; kc++) {
        if (kc < 7) { LOAD_STAGE(kc + 1, (kc + 1) & 1); CP_WAIT1(); }
        else        { CP_WAIT0(); }
        __syncthreads();
        uint32_t stg = sb + (kc & 1) * STG;
#pragma unroll
        for (int ks = 0; ks < 2; ks++) {
            uint32_t coff = (uint32_t)((ks * 16 + lc) * 2);
            uint32_t bg[8];
#pragma unroll
            for (int h = 0; h < 2; h++) {
                uint32_t bd = stg + 2 * ARR + (uint32_t)((wn * 32 + h * 16 + lr) * ROWB) + coff;
                ldsm4(bg[h * 4 + 0], bg[h * 4 + 1], bg[h * 4 + 2], bg[h * 4 + 3], bd);
            }
#pragma unroll
            for (int mi = 0; mi < 4; mi++) {
                uint32_t ad = stg + (uint32_t)((wm * 64 + mi * 16 + lr) * ROWB) + coff;
                uint32_t ah0, ah1, ah2, ah3, al0, al1, al2, al3;
                ldsm4(ah0, ah1, ah2, ah3, ad);
                ldsm4(al0, al1, al2, al3, ad + ARR);
#pragma unroll
                for (int ni = 0; ni < 4; ni++) {
                    int h = ni >> 1, s2 = ni & 1;
                    uint32_t b0 = bg[h * 4 + s2], b1 = bg[h * 4 + s2 + 2];
                    mma_fp(acc[mi][ni], ah0, ah1, ah2, ah3, b0, b1);
                    mma_fp(acc[mi][ni], al0, al1, al2, al3, b0, b1);
                }
            }
        }
        __syncthreads();
    }

    int g = lane >> 2, tc = lane & 3;
#pragma unroll
    for (int mi = 0; mi < 4; mi++) {
        size_t r0 = q0 + (size_t)(wm * 64 + mi * 16 + g);
        size_t r1 = r0 + 8;
#pragma unroll
        for (int ni = 0; ni < 4; ni++) {
            size_t col = n0 + (size_t)(wn * 32 + ni * 8 + tc * 2);
            *(float2*)(out + r0 * NKEYS + col) = make_float2(acc[mi][ni][0], acc[mi][ni][1]);
            *(float2*)(out + r1 * NKEYS + col) = make_float2(acc[mi][ni][2], acc[mi][ni][3]);
        }
    }
}

extern "C" void kernel_launch(void* const* d_in, const int* in_sizes, int n_in,
                              void* d_out, int out_size) {
    const float* query    = (const float*)d_in[0];
    const float* keys     = (const float*)d_in[1];
    const float* codebook = (const float*)d_in[2];
    const float* S        = (const float*)d_in[3];
    float* out = (float*)d_out;

    zeroq_kernel<<<1, 32>>>();
    build_S_kernel<<<64, 256>>>(S);

    int shA = (128 * 129 + 256) * 4;
    cudaFuncSetAttribute(build_A_kernel, cudaFuncAttributeMaxDynamicSharedMemorySize, shA);
    build_A_kernel<<<64, 256, shA>>>(query, S);

    prep1_kernel<<<NKEYS / 8, 256>>>(keys, codebook);

    int shP = 4 * PARR;  // 139264
    cudaFuncSetAttribute(proj_kernel, cudaFuncAttributeMaxDynamicSharedMemorySize, shP);
    proj_kernel<<<NKEYS / 128, 256, shP>>>();

    fixup_kernel<<<256, 256>>>(keys, codebook, S);

    int shG = 2 * STG;   // 61440
    cudaFuncSetAttribute(gemm_kernel, cudaFuncAttributeMaxDynamicSharedMemorySize, shG);
    dim3 grid(QDIM / 128, NKEYS / 128);
    gemm_kernel<<<grid, 256, shG>>>(out);
}

// round 14
// speedup vs baseline: 1.7997x; 1.3328x over previous
#include <cuda_runtime.h>
#include <cuda_bf16.h>
#include <cuda_fp16.h>
#include <math.h>
#include <stdint.h>

#define NKEYS 131072
#define DDIM 128
#define QDIM 512
#define KTOT 256
#define MAXQ 262144
#define SIGN_TH 5e-4f

__device__ __half        g_B [(size_t)NKEYS * KTOT];   // [vn*x_mse | coef*sign] fp16
__device__ __nv_bfloat16 g_Rh[(size_t)NKEYS * DDIM];
__device__ __nv_bfloat16 g_Rl[(size_t)NKEYS * DDIM];
__device__ float         g_C [(size_t)NKEYS];
__device__ float         g_Rn[(size_t)NKEYS];
__device__ __nv_bfloat16 g_Sh[DDIM * DDIM];
__device__ __nv_bfloat16 g_Sl[DDIM * DDIM];
__device__ __half        g_A [(size_t)QDIM * KTOT];    // [q | Sq] fp16
__device__ int           g_qcount;
__device__ uint32_t      g_queue[MAXQ];

__device__ __forceinline__ uint32_t smem_u32(const void* p) {
    uint32_t a;
    asm("{ .reg .u64 t; cvta.to.shared.u64 t, %1; cvt.u32.u64 %0, t; }" : "=r"(a) : "l"(p));
    return a;
}
__device__ __forceinline__ void cp_async16(uint32_t dst, const void* src) {
    uint64_t g;
    asm("cvta.to.global.u64 %0, %1;" : "=l"(g) : "l"(src));
    asm volatile("cp.async.cg.shared.global [%0], [%1], 16;" :: "r"(dst), "l"(g));
}
#define CP_COMMIT() asm volatile("cp.async.commit_group;" ::: "memory")
#define CP_WAIT1()  asm volatile("cp.async.wait_group 1;" ::: "memory")
#define CP_WAIT0()  asm volatile("cp.async.wait_group 0;" ::: "memory")

__device__ __forceinline__ void ldsm4(uint32_t& r0, uint32_t& r1, uint32_t& r2,
                                      uint32_t& r3, uint32_t addr) {
    asm volatile("ldmatrix.sync.aligned.m8n8.x4.shared.b16 {%0,%1,%2,%3}, [%4];"
                 : "=r"(r0), "=r"(r1), "=r"(r2), "=r"(r3) : "r"(addr));
}
__device__ __forceinline__ void mma_bf(float* c, uint32_t a0, uint32_t a1,
                                       uint32_t a2, uint32_t a3,
                                       uint32_t b0, uint32_t b1) {
    asm volatile(
        "mma.sync.aligned.m16n8k16.row.col.f32.bf16.bf16.f32 "
        "{%0,%1,%2,%3}, {%4,%5,%6,%7}, {%8,%9}, {%0,%1,%2,%3};"
        : "+f"(c[0]), "+f"(c[1]), "+f"(c[2]), "+f"(c[3])
        : "r"(a0), "r"(a1), "r"(a2), "r"(a3), "r"(b0), "r"(b1));
}
__device__ __forceinline__ void mma_fp(float* c, uint32_t a0, uint32_t a1,
                                       uint32_t a2, uint32_t a3,
                                       uint32_t b0, uint32_t b1) {
    asm volatile(
        "mma.sync.aligned.m16n8k16.row.col.f32.f16.f16.f32 "
        "{%0,%1,%2,%3}, {%4,%5,%6,%7}, {%8,%9}, {%0,%1,%2,%3};"
        : "+f"(c[0]), "+f"(c[1]), "+f"(c[2]), "+f"(c[3])
        : "r"(a0), "r"(a1), "r"(a2), "r"(a3), "r"(b0), "r"(b1));
}
__device__ __forceinline__ void bf16split(float v, __nv_bfloat16& h, __nv_bfloat16& l) {
    h = __float2bfloat16(v);
    l = __float2bfloat16(v - __bfloat162float(h));
}
__device__ __forceinline__ uint32_t pack2b(__nv_bfloat16 a, __nv_bfloat16 b) {
    union { __nv_bfloat16 h[2]; uint32_t u; } t;
    t.h[0] = a; t.h[1] = b;
    return t.u;
}
__device__ __forceinline__ uint32_t pack2h(__half a, __half b) {
    union { __half h[2]; uint32_t u; } t;
    t.h[0] = a; t.h[1] = b;
    return t.u;
}
__device__ __forceinline__ void enqueue(uint32_t n, uint32_t j) {
    uint32_t idx = (uint32_t)atomicAdd(&g_qcount, 1);
    if (idx < MAXQ) g_queue[idx] = (n << 7) | j;
}

__global__ void zeroq_kernel() { if (threadIdx.x == 0) g_qcount = 0; }

__global__ void build_S_kernel(const float* __restrict__ S) {
    int i = blockIdx.x * 256 + threadIdx.x;
    __nv_bfloat16 h, l;
    bf16split(S[i], h, l);
    g_Sh[i] = h; g_Sl[i] = l;
}

// --- A = [query | query @ S^T] -> fp16 ---
__global__ __launch_bounds__(256) void build_A_kernel(const float* __restrict__ query,
                                                      const float* __restrict__ S) {
    extern __shared__ float sh[];
    float* St = sh;
    float* qsh = sh + 128 * 129;
    int t = threadIdx.x, j = t & 127, qs = t >> 7;
    for (int idx = t; idx < 128 * 128; idx += 256) {
        int jj = idx >> 7, ii = idx & 127;
        St[ii * 129 + jj] = S[idx];
    }
    __syncthreads();
    int q0 = blockIdx.x * 8;
    for (int qq = 0; qq < 4; qq++) {
        int q = q0 + qq * 2 + qs;
        float qv = query[q * DDIM + j];
        qsh[qs * 128 + j] = qv;
        __syncthreads();
        float acc = 0.f;
#pragma unroll 8
        for (int i = 0; i < 128; i++) acc += qsh[qs * 128 + i] * St[i * 129 + j];
        g_A[(size_t)q * KTOT + j] = __float2half(qv);
        g_A[(size_t)q * KTOT + 128 + j] = __float2half(acc);
        __syncthreads();
    }
}

// --- prep1: warp-per-key ---
__global__ __launch_bounds__(256) void prep1_kernel(const float* __restrict__ keys,
                                                    const float* __restrict__ cb) {
    int lane = threadIdx.x & 31, w = threadIdx.x >> 5;
    size_t n = (size_t)blockIdx.x * 8 + w;
    float c0 = cb[0], c1 = cb[1], c2 = cb[2], c3 = cb[3];
    float m01 = 0.5f * (c0 + c1), m12 = 0.5f * (c1 + c2), m23 = 0.5f * (c2 + c3);

    float4 kv = *(const float4*)(keys + n * DDIM + lane * 4);
    float ss = kv.x * kv.x + kv.y * kv.y + kv.z * kv.z + kv.w * kv.w;
#pragma unroll
    for (int o = 16; o; o >>= 1) ss += __shfl_xor_sync(0xffffffffu, ss, o);
    float vn = sqrtf(ss);
    float inv = 1.f / (vn + 1e-8f);

    float x[4] = {kv.x * inv, kv.y * inv, kv.z * inv, kv.w * inv};
    float r[4], rr = 0.f;
    __half bq[4];
#pragma unroll
    for (int i = 0; i < 4; i++) {
        float xm = (x[i] >= m12) ? ((x[i] >= m23) ? c3 : c2)
                                 : ((x[i] >= m01) ? c1 : c0);
        r[i] = x[i] - xm;
        rr += r[i] * r[i];
        bq[i] = __float2half(vn * xm);
    }
    *(uint2*)&g_B[n * KTOT + lane * 4] = make_uint2(pack2h(bq[0], bq[1]), pack2h(bq[2], bq[3]));

#pragma unroll
    for (int o = 16; o; o >>= 1) rr += __shfl_xor_sync(0xffffffffu, rr, o);
    float rn = sqrtf(rr);

    __nv_bfloat16 rh[4], rl[4];
#pragma unroll
    for (int i = 0; i < 4; i++) bf16split(r[i], rh[i], rl[i]);
    *(uint2*)&g_Rh[n * DDIM + lane * 4] = make_uint2(pack2b(rh[0], rh[1]), pack2b(rh[2], rh[3]));
    *(uint2*)&g_Rl[n * DDIM + lane * 4] = make_uint2(pack2b(rl[0], rl[1]), pack2b(rl[2], rl[3]));
    if (lane == 0) {
        g_C[n]  = vn * rn * 0.009797554543986288f;  // sqrt(pi/2)/128
        g_Rn[n] = rn;
    }
}

// --- proj: sign(R @ S^T)*coef -> g_B[:,128:256] (fp16); enqueue ambiguous ---
#define PROW 272
#define PARR 34816

__global__ __launch_bounds__(256, 1) void proj_kernel() {
    extern __shared__ __align__(16) char sm[];
    uint32_t sb = smem_u32(sm);
    int tid = threadIdx.x, wid = tid >> 5, lane = tid & 31;
    int wm = wid >> 2, wn = wid & 3;
    size_t n0 = (size_t)blockIdx.x * 128;

#pragma unroll
    for (int it = 0; it < 8; it++) {
        int idx = tid + it * 256;
        int row = idx >> 4, c16 = idx & 15;
        uint32_t d = (uint32_t)(row * PROW + c16 * 16);
        size_t ro = (n0 + (size_t)row) * DDIM + c16 * 8;
        cp_async16(sb + d,            g_Rh + ro);
        cp_async16(sb + PARR + d,     g_Rl + ro);
        size_t so = (size_t)row * DDIM + c16 * 8;
        cp_async16(sb + 2 * PARR + d, g_Sh + so);
        cp_async16(sb + 3 * PARR + d, g_Sl + so);
    }
    CP_COMMIT();

    float acc[4][4][4];
#pragma unroll
    for (int i = 0; i < 4; i++)
#pragma unroll
        for (int j = 0; j < 4; j++)
#pragma unroll
            for (int k = 0; k < 4; k++) acc[i][j][k] = 0.f;

    CP_WAIT0();
    __syncthreads();

    int lr = lane & 15, lc = (lane >> 4) * 8;
#pragma unroll
    for (int ks = 0; ks < 8; ks++) {
        uint32_t coff = (uint32_t)((ks * 16 + lc) * 2);
        uint32_t bh[8], bl[8];
#pragma unroll
        for (int h = 0; h < 2; h++) {
            uint32_t bd = sb + 2 * PARR + (uint32_t)((wn * 32 + h * 16 + lr) * PROW) + coff;
            ldsm4(bh[h * 4 + 0], bh[h * 4 + 1], bh[h * 4 + 2], bh[h * 4 + 3], bd);
            ldsm4(bl[h * 4 + 0], bl[h * 4 + 1], bl[h * 4 + 2], bl[h * 4 + 3], bd + PARR);
        }
#pragma unroll
        for (int mi = 0; mi < 4; mi++) {
            uint32_t ad = sb + (uint32_t)((wm * 64 + mi * 16 + lr) * PROW) + coff;
            uint32_t ah0, ah1, ah2, ah3, al0, al1, al2, al3;
            ldsm4(ah0, ah1, ah2, ah3, ad);
            ldsm4(al0, al1, al2, al3, ad + PARR);
#pragma unroll
            for (int ni = 0; ni < 4; ni++) {
                int h = ni >> 1, s2 = ni & 1;
                uint32_t b0h = bh[h * 4 + s2], b1h = bh[h * 4 + s2 + 2];
                uint32_t b0l = bl[h * 4 + s2], b1l = bl[h * 4 + s2 + 2];
                mma_bf(acc[mi][ni], ah0, ah1, ah2, ah3, b0h, b1h);
                mma_bf(acc[mi][ni], al0, al1, al2, al3, b0h, b1h);
                mma_bf(acc[mi][ni], ah0, ah1, ah2, ah3, b0l, b1l);
            }
        }
    }

    int g = lane >> 2, tc = lane & 3;
#pragma unroll
    for (int mi = 0; mi < 4; mi++) {
        size_t r0 = n0 + (size_t)(wm * 64 + mi * 16 + g);
        size_t r1 = r0 + 8;
        float tA = g_Rn[r0] * SIGN_TH, tB = g_Rn[r1] * SIGN_TH;
        __half cA = __float2half(g_C[r0]), cB = __float2half(g_C[r1]);
#pragma unroll
        for (int ni = 0; ni < 4; ni++) {
            int j0 = wn * 32 + ni * 8 + tc * 2;
            bool p0 = acc[mi][ni][0] >= 0.f, p1 = acc[mi][ni][1] >= 0.f;
            bool p2 = acc[mi][ni][2] >= 0.f, p3 = acc[mi][ni][3] >= 0.f;
            *(uint32_t*)&g_B[r0 * KTOT + 128 + j0] =
                pack2h(p0 ? cA : __hneg(cA), p1 ? cA : __hneg(cA));
            *(uint32_t*)&g_B[r1 * KTOT + 128 + j0] =
                pack2h(p2 ? cB : __hneg(cB), p3 ? cB : __hneg(cB));
            if (fabsf(acc[mi][ni][0]) < tA) enqueue((uint32_t)r0, (uint32_t)j0);
            if (fabsf(acc[mi][ni][1]) < tA) enqueue((uint32_t)r0, (uint32_t)(j0 + 1));
            if (fabsf(acc[mi][ni][2]) < tB) enqueue((uint32_t)r1, (uint32_t)j0);
            if (fabsf(acc[mi][ni][3]) < tB) enqueue((uint32_t)r1, (uint32_t)(j0 + 1));
        }
    }
}

// --- fixup: recompute ambiguous signs in exact fp32 ---
__global__ __launch_bounds__(256) void fixup_kernel(const float* __restrict__ keys,
                                                    const float* __restrict__ cb,
                                                    const float* __restrict__ S) {
    int lane = threadIdx.x & 31;
    int w = (blockIdx.x * blockDim.x + threadIdx.x) >> 5;
    int nw = (gridDim.x * blockDim.x) >> 5;
    int cnt = g_qcount;
    if (cnt > MAXQ) cnt = MAXQ;
    float c0 = cb[0], c1 = cb[1], c2 = cb[2], c3 = cb[3];
    float m01 = 0.5f * (c0 + c1), m12 = 0.5f * (c1 + c2), m23 = 0.5f * (c2 + c3);

    for (int e = w; e < cnt; e += nw) {
        uint32_t pk = g_queue[e];
        size_t n = (size_t)(pk >> 7);
        uint32_t j = pk & 127u;
        float4 kv = *(const float4*)(keys + n * DDIM + lane * 4);
        float ss = kv.x * kv.x + kv.y * kv.y + kv.z * kv.z + kv.w * kv.w;
#pragma unroll
        for (int o = 16; o; o >>= 1) ss += __shfl_xor_sync(0xffffffffu, ss, o);
        float vn = sqrtf(ss);
        float inv = 1.f / (vn + 1e-8f);
        float x[4] = {kv.x * inv, kv.y * inv, kv.z * inv, kv.w * inv};
        float4 sv = *(const float4*)(S + (size_t)j * DDIM + lane * 4);
        float svv[4] = {sv.x, sv.y, sv.z, sv.w};
        float dot = 0.f;
#pragma unroll
        for (int i = 0; i < 4; i++) {
            float xm = (x[i] >= m12) ? ((x[i] >= m23) ? c3 : c2)
                                     : ((x[i] >= m01) ? c1 : c0);
            dot += (x[i] - xm) * svv[i];
        }
#pragma unroll
        for (int o = 16; o; o >>= 1) dot += __shfl_xor_sync(0xffffffffu, dot, o);
        if (lane == 0) {
            float coef = g_C[n];
            g_B[n * KTOT + 128 + j] = __float2half((dot >= 0.f) ? coef : -coef);
        }
    }
}

// --- main GEMM: fp16, 1 term (A.B), K=256, occ 2 ---
#define ROWB 80
#define ARR  10240
#define STG  20480    // 2*ARR

__global__ __launch_bounds__(256, 2) void gemm_kernel(float* __restrict__ out) {
    extern __shared__ __align__(16) char sm[];
    uint32_t sb = smem_u32(sm);
    int tid = threadIdx.x, wid = tid >> 5, lane = tid & 31;
    int wm = wid >> 2, wn = wid & 3;
    size_t q0 = (size_t)blockIdx.x * 128;
    size_t n0 = (size_t)blockIdx.y * 128;

    float acc[4][4][4];
#pragma unroll
    for (int i = 0; i < 4; i++)
#pragma unroll
        for (int j = 0; j < 4; j++)
#pragma unroll
            for (int k = 0; k < 4; k++) acc[i][j][k] = 0.f;

#define LOAD_STAGE(KC, S_)                                                    \
    do {                                                                      \
        uint32_t stg_ = sb + (S_) * STG;                                      \
        int kofs_ = (KC) * 32;                                                \
        _Pragma("unroll")                                                     \
        for (int it = 0; it < 2; it++) {                                      \
            int idx = tid + it * 256;                                         \
            int row = idx >> 2, c16 = idx & 3;                                \
            uint32_t d = (uint32_t)(row * ROWB + c16 * 16);                   \
            size_t ao = (q0 + (size_t)row) * KTOT + kofs_ + c16 * 8;          \
            cp_async16(stg_ + d,       g_A + ao);                             \
            size_t bo = (n0 + (size_t)row) * KTOT + kofs_ + c16 * 8;          \
            cp_async16(stg_ + ARR + d, g_B + bo);                             \
        }                                                                     \
        CP_COMMIT();                                                          \
    } while (0)

    LOAD_STAGE(0, 0);
    int lr = lane & 15, lc = (lane >> 4) * 8;

    for (int kc = 0; kc < 8; kc++) {
        if (kc < 7) { LOAD_STAGE(kc + 1, (kc + 1) & 1); CP_WAIT1(); }
        else        { CP_WAIT0(); }
        __syncthreads();
        uint32_t stg = sb + (kc & 1) * STG;
#pragma unroll
        for (int ks = 0; ks < 2; ks++) {
            uint32_t coff = (uint32_t)((ks * 16 + lc) * 2);
            uint32_t bg[8];
#pragma unroll
            for (int h = 0; h < 2; h++) {
                uint32_t bd = stg + ARR + (uint32_t)((wn * 32 + h * 16 + lr) * ROWB) + coff;
                ldsm4(bg[h * 4 + 0], bg[h * 4 + 1], bg[h * 4 + 2], bg[h * 4 + 3], bd);
            }
#pragma unroll
            for (int mi = 0; mi < 4; mi++) {
                uint32_t ad = stg + (uint32_t)((wm * 64 + mi * 16 + lr) * ROWB) + coff;
                uint32_t a0, a1, a2, a3;
                ldsm4(a0, a1, a2, a3, ad);
#pragma unroll
                for (int ni = 0; ni < 4; ni++) {
                    int h = ni >> 1, s2 = ni & 1;
                    uint32_t b0 = bg[h * 4 + s2], b1 = bg[h * 4 + s2 + 2];
                    mma_fp(acc[mi][ni], a0, a1, a2, a3, b0, b1);
                }
            }
        }
        __syncthreads();
    }

    int g = lane >> 2, tc = lane & 3;
#pragma unroll
    for (int mi = 0; mi < 4; mi++) {
        size_t r0 = q0 + (size_t)(wm * 64 + mi * 16 + g);
        size_t r1 = r0 + 8;
#pragma unroll
        for (int ni = 0; ni < 4; ni++) {
            size_t col = n0 + (size_t)(wn * 32 + ni * 8 + tc * 2);
            *(float2*)(out + r0 * NKEYS + col) = make_float2(acc[mi][ni][0], acc[mi][ni][1]);
            *(float2*)(out + r1 * NKEYS + col) = make_float2(acc[mi][ni][2], acc[mi][ni][3]);
        }
    }
}

extern "C" void kernel_launch(void* const* d_in, const int* in_sizes, int n_in,
                              void* d_out, int out_size) {
    const float* query    = (const float*)d_in[0];
    const float* keys     = (const float*)d_in[1];
    const float* codebook = (const float*)d_in[2];
    const float* S        = (const float*)d_in[3];
    float* out = (float*)d_out;

    zeroq_kernel<<<1, 32>>>();
    build_S_kernel<<<64, 256>>>(S);

    int shA = (128 * 129 + 256) * 4;
    cudaFuncSetAttribute(build_A_kernel, cudaFuncAttributeMaxDynamicSharedMemorySize, shA);
    build_A_kernel<<<64, 256, shA>>>(query, S);

    prep1_kernel<<<NKEYS / 8, 256>>>(keys, codebook);

    int shP = 4 * PARR;  // 139264
    cudaFuncSetAttribute(proj_kernel, cudaFuncAttributeMaxDynamicSharedMemorySize, shP);
    proj_kernel<<<NKEYS / 128, 256, shP>>>();

    fixup_kernel<<<256, 256>>>(keys, codebook, S);

    int shG = 2 * STG;   // 40960
    cudaFuncSetAttribute(gemm_kernel, cudaFuncAttributeMaxDynamicSharedMemorySize, shG);
    dim3 grid(QDIM / 128, NKEYS / 128);
    gemm_kernel<<<grid, 256, shG>>>(out);
}

// round 16
// speedup vs baseline: 2.0445x; 1.1360x over previous
#include <cuda_runtime.h>
#include <cuda_bf16.h>
#include <cuda_fp16.h>
#include <math.h>
#include <stdint.h>

#define NKEYS 131072
#define DDIM 128
#define QDIM 512
#define KTOT 256
#define MAXQ 262144
#define SIGN_TH 1.5e-3f

__device__ __half        g_B [(size_t)NKEYS * KTOT];   // [vn*x_mse | coef*sign] fp16
__device__ __half        g_R [(size_t)NKEYS * DDIM];   // residual fp16
__device__ float         g_C [(size_t)NKEYS];
__device__ float         g_Rn[(size_t)NKEYS];
__device__ __half        g_Sh[DDIM * DDIM];            // S fp16 hi
__device__ __half        g_Sl[DDIM * DDIM];            // S fp16 lo
__device__ float         g_St[DDIM * DDIM];            // S^T fp32 (St[i*128+j] = S[j][i])
__device__ __half        g_A [(size_t)QDIM * KTOT];    // [q | Sq] fp16
__device__ int           g_qcount;
__device__ uint32_t      g_queue[MAXQ];

__device__ __forceinline__ uint32_t smem_u32(const void* p) {
    uint32_t a;
    asm("{ .reg .u64 t; cvta.to.shared.u64 t, %1; cvt.u32.u64 %0, t; }" : "=r"(a) : "l"(p));
    return a;
}
__device__ __forceinline__ void cp_async16(uint32_t dst, const void* src) {
    uint64_t g;
    asm("cvta.to.global.u64 %0, %1;" : "=l"(g) : "l"(src));
    asm volatile("cp.async.cg.shared.global [%0], [%1], 16;" :: "r"(dst), "l"(g));
}
#define CP_COMMIT() asm volatile("cp.async.commit_group;" ::: "memory")
#define CP_WAIT1()  asm volatile("cp.async.wait_group 1;" ::: "memory")
#define CP_WAIT0()  asm volatile("cp.async.wait_group 0;" ::: "memory")

__device__ __forceinline__ void ldsm4(uint32_t& r0, uint32_t& r1, uint32_t& r2,
                                      uint32_t& r3, uint32_t addr) {
    asm volatile("ldmatrix.sync.aligned.m8n8.x4.shared.b16 {%0,%1,%2,%3}, [%4];"
                 : "=r"(r0), "=r"(r1), "=r"(r2), "=r"(r3) : "r"(addr));
}
__device__ __forceinline__ void mma_fp(float* c, uint32_t a0, uint32_t a1,
                                       uint32_t a2, uint32_t a3,
                                       uint32_t b0, uint32_t b1) {
    asm volatile(
        "mma.sync.aligned.m16n8k16.row.col.f32.f16.f16.f32 "
        "{%0,%1,%2,%3}, {%4,%5,%6,%7}, {%8,%9}, {%0,%1,%2,%3};"
        : "+f"(c[0]), "+f"(c[1]), "+f"(c[2]), "+f"(c[3])
        : "r"(a0), "r"(a1), "r"(a2), "r"(a3), "r"(b0), "r"(b1));
}
__device__ __forceinline__ uint32_t pack2h(__half a, __half b) {
    union { __half h[2]; uint32_t u; } t;
    t.h[0] = a; t.h[1] = b;
    return t.u;
}
__device__ __forceinline__ void enqueue(uint32_t n, uint32_t j) {
    uint32_t idx = (uint32_t)atomicAdd(&g_qcount, 1);
    if (idx < MAXQ) g_queue[idx] = (n << 7) | j;
}

// --- prep1: warp-per-key; blocks 0..63 also split/transpose S; block 0 zeroes queue ---
__global__ __launch_bounds__(256) void prep1_kernel(const float* __restrict__ keys,
                                                    const float* __restrict__ cb,
                                                    const float* __restrict__ S) {
    int tid = threadIdx.x;
    if (blockIdx.x < 64) {
        int i = blockIdx.x * 256 + tid;
        float sv = S[i];
        __half h = __float2half(sv);
        __half l = __float2half(sv - __half2float(h));
        g_Sh[i] = h; g_Sl[i] = l;
        int j = i >> 7, ii = i & 127;
        g_St[ii * 128 + j] = sv;
        if (i == 0) g_qcount = 0;
    }
    int lane = tid & 31, w = tid >> 5;
    size_t n = (size_t)blockIdx.x * 8 + w;
    float c0 = cb[0], c1 = cb[1], c2 = cb[2], c3 = cb[3];
    float m01 = 0.5f * (c0 + c1), m12 = 0.5f * (c1 + c2), m23 = 0.5f * (c2 + c3);

    float4 kv = *(const float4*)(keys + n * DDIM + lane * 4);
    float ss = kv.x * kv.x + kv.y * kv.y + kv.z * kv.z + kv.w * kv.w;
#pragma unroll
    for (int o = 16; o; o >>= 1) ss += __shfl_xor_sync(0xffffffffu, ss, o);
    float vn = sqrtf(ss);
    float inv = 1.f / (vn + 1e-8f);

    float x[4] = {kv.x * inv, kv.y * inv, kv.z * inv, kv.w * inv};
    float r[4], rr = 0.f;
    __half bq[4], rq[4];
#pragma unroll
    for (int i = 0; i < 4; i++) {
        float xm = (x[i] >= m12) ? ((x[i] >= m23) ? c3 : c2)
                                 : ((x[i] >= m01) ? c1 : c0);
        r[i] = x[i] - xm;
        rr += r[i] * r[i];
        bq[i] = __float2half(vn * xm);
        rq[i] = __float2half(r[i]);
    }
    *(uint2*)&g_B[n * KTOT + lane * 4] = make_uint2(pack2h(bq[0], bq[1]), pack2h(bq[2], bq[3]));
    *(uint2*)&g_R[n * DDIM + lane * 4] = make_uint2(pack2h(rq[0], rq[1]), pack2h(rq[2], rq[3]));

#pragma unroll
    for (int o = 16; o; o >>= 1) rr += __shfl_xor_sync(0xffffffffu, rr, o);
    float rn = sqrtf(rr);
    if (lane == 0) {
        g_C[n]  = vn * rn * 0.009797554543986288f;  // sqrt(pi/2)/128
        g_Rn[n] = rn;
    }
}

// --- build_A: 512 blocks, 1 query each; coalesced reads of transposed S ---
__global__ __launch_bounds__(128) void build_A_kernel(const float* __restrict__ query) {
    __shared__ float qsh[128];
    int q = blockIdx.x, j = threadIdx.x;
    float qv = query[q * DDIM + j];
    qsh[j] = qv;
    __syncthreads();
    float acc = 0.f;
#pragma unroll 16
    for (int i = 0; i < 128; i++) acc += qsh[i] * g_St[i * 128 + j];
    g_A[(size_t)q * KTOT + j] = __float2half(qv);
    g_A[(size_t)q * KTOT + 128 + j] = __float2half(acc);
}

// --- proj: sign(R @ S^T)*coef -> g_B[:,128:256]; fp16 2-term; occ 2 ---
#define PROW 272
#define PARR 34816

__global__ __launch_bounds__(256, 2) void proj_kernel() {
    extern __shared__ __align__(16) char sm[];
    uint32_t sb = smem_u32(sm);
    int tid = threadIdx.x, wid = tid >> 5, lane = tid & 31;
    int wm = wid >> 2, wn = wid & 3;
    size_t n0 = (size_t)blockIdx.x * 128;

#pragma unroll
    for (int it = 0; it < 8; it++) {
        int idx = tid + it * 256;
        int row = idx >> 4, c16 = idx & 15;
        uint32_t d = (uint32_t)(row * PROW + c16 * 16);
        size_t ro = (n0 + (size_t)row) * DDIM + c16 * 8;
        cp_async16(sb + d,            g_R + ro);
        size_t so = (size_t)row * DDIM + c16 * 8;
        cp_async16(sb + PARR + d,     g_Sh + so);
        cp_async16(sb + 2 * PARR + d, g_Sl + so);
    }
    CP_COMMIT();

    float acc[4][4][4];
#pragma unroll
    for (int i = 0; i < 4; i++)
#pragma unroll
        for (int j = 0; j < 4; j++)
#pragma unroll
            for (int k = 0; k < 4; k++) acc[i][j][k] = 0.f;

    CP_WAIT0();
    __syncthreads();

    int lr = lane & 15, lc = (lane >> 4) * 8;
#pragma unroll
    for (int ks = 0; ks < 8; ks++) {
        uint32_t coff = (uint32_t)((ks * 16 + lc) * 2);
        uint32_t bh[8], bl[8];
#pragma unroll
        for (int h = 0; h < 2; h++) {
            uint32_t bd = sb + PARR + (uint32_t)((wn * 32 + h * 16 + lr) * PROW) + coff;
            ldsm4(bh[h * 4 + 0], bh[h * 4 + 1], bh[h * 4 + 2], bh[h * 4 + 3], bd);
            ldsm4(bl[h * 4 + 0], bl[h * 4 + 1], bl[h * 4 + 2], bl[h * 4 + 3], bd + PARR);
        }
#pragma unroll
        for (int mi = 0; mi < 4; mi++) {
            uint32_t ad = sb + (uint32_t)((wm * 64 + mi * 16 + lr) * PROW) + coff;
            uint32_t a0, a1, a2, a3;
            ldsm4(a0, a1, a2, a3, ad);
#pragma unroll
            for (int ni = 0; ni < 4; ni++) {
                int h = ni >> 1, s2 = ni & 1;
                mma_fp(acc[mi][ni], a0, a1, a2, a3, bh[h * 4 + s2], bh[h * 4 + s2 + 2]);
                mma_fp(acc[mi][ni], a0, a1, a2, a3, bl[h * 4 + s2], bl[h * 4 + s2 + 2]);
            }
        }
    }

    int g = lane >> 2, tc = lane & 3;
#pragma unroll
    for (int mi = 0; mi < 4; mi++) {
        size_t r0 = n0 + (size_t)(wm * 64 + mi * 16 + g);
        size_t r1 = r0 + 8;
        float tA = g_Rn[r0] * SIGN_TH, tB = g_Rn[r1] * SIGN_TH;
        __half cA = __float2half(g_C[r0]), cB = __float2half(g_C[r1]);
#pragma unroll
        for (int ni = 0; ni < 4; ni++) {
            int j0 = wn * 32 + ni * 8 + tc * 2;
            bool p0 = acc[mi][ni][0] >= 0.f, p1 = acc[mi][ni][1] >= 0.f;
            bool p2 = acc[mi][ni][2] >= 0.f, p3 = acc[mi][ni][3] >= 0.f;
            *(uint32_t*)&g_B[r0 * KTOT + 128 + j0] =
                pack2h(p0 ? cA : __hneg(cA), p1 ? cA : __hneg(cA));
            *(uint32_t*)&g_B[r1 * KTOT + 128 + j0] =
                pack2h(p2 ? cB : __hneg(cB), p3 ? cB : __hneg(cB));
            if (fabsf(acc[mi][ni][0]) < tA) enqueue((uint32_t)r0, (uint32_t)j0);
            if (fabsf(acc[mi][ni][1]) < tA) enqueue((uint32_t)r0, (uint32_t)(j0 + 1));
            if (fabsf(acc[mi][ni][2]) < tB) enqueue((uint32_t)r1, (uint32_t)j0);
            if (fabsf(acc[mi][ni][3]) < tB) enqueue((uint32_t)r1, (uint32_t)(j0 + 1));
        }
    }
}

// --- fixup: recompute ambiguous signs in exact fp32 ---
__global__ __launch_bounds__(256) void fixup_kernel(const float* __restrict__ keys,
                                                    const float* __restrict__ cb,
                                                    const float* __restrict__ S) {
    int lane = threadIdx.x & 31;
    int w = (blockIdx.x * blockDim.x + threadIdx.x) >> 5;
    int nw = (gridDim.x * blockDim.x) >> 5;
    int cnt = g_qcount;
    if (cnt > MAXQ) cnt = MAXQ;
    float c0 = cb[0], c1 = cb[1], c2 = cb[2], c3 = cb[3];
    float m01 = 0.5f * (c0 + c1), m12 = 0.5f * (c1 + c2), m23 = 0.5f * (c2 + c3);

    for (int e = w; e < cnt; e += nw) {
        uint32_t pk = g_queue[e];
        size_t n = (size_t)(pk >> 7);
        uint32_t j = pk & 127u;
        float4 kv = *(const float4*)(keys + n * DDIM + lane * 4);
        float ss = kv.x * kv.x + kv.y * kv.y + kv.z * kv.z + kv.w * kv.w;
#pragma unroll
        for (int o = 16; o; o >>= 1) ss += __shfl_xor_sync(0xffffffffu, ss, o);
        float vn = sqrtf(ss);
        float inv = 1.f / (vn + 1e-8f);
        float x[4] = {kv.x * inv, kv.y * inv, kv.z * inv, kv.w * inv};
        float4 sv = *(const float4*)(S + (size_t)j * DDIM + lane * 4);
        float svv[4] = {sv.x, sv.y, sv.z, sv.w};
        float dot = 0.f;
#pragma unroll
        for (int i = 0; i < 4; i++) {
            float xm = (x[i] >= m12) ? ((x[i] >= m23) ? c3 : c2)
                                     : ((x[i] >= m01) ? c1 : c0);
            dot += (x[i] - xm) * svv[i];
        }
#pragma unroll
        for (int o = 16; o; o >>= 1) dot += __shfl_xor_sync(0xffffffffu, dot, o);
        if (lane == 0) {
            float coef = g_C[n];
            g_B[n * KTOT + 128 + j] = __float2half((dot >= 0.f) ? coef : -coef);
        }
    }
}

// --- main GEMM: fp16, 1 term (A.B), K=256, occ 2 ---
#define ROWB 80
#define ARR  10240
#define STG  20480    // 2*ARR

__global__ __launch_bounds__(256, 2) void gemm_kernel(float* __restrict__ out) {
    extern __shared__ __align__(16) char sm[];
    uint32_t sb = smem_u32(sm);
    int tid = threadIdx.x, wid = tid >> 5, lane = tid & 31;
    int wm = wid >> 2, wn = wid & 3;
    size_t q0 = (size_t)blockIdx.x * 128;
    size_t n0 = (size_t)blockIdx.y * 128;

    float acc[4][4][4];
#pragma unroll
    for (int i = 0; i < 4; i++)
#pragma unroll
        for (int j = 0; j < 4; j++)
#pragma unroll
            for (int k = 0; k < 4; k++) acc[i][j][k] = 0.f;

#define LOAD_STAGE(KC, S_)                                                    \
    do {                                                                      \
        uint32_t stg_ = sb + (S_) * STG;                                      \
        int kofs_ = (KC) * 32;                                                \
        _Pragma("unroll")                                                     \
        for (int it = 0; it < 2; it++) {                                      \
            int idx = tid + it * 256;                                         \
            int row = idx >> 2, c16 = idx & 3;                                \
            uint32_t d = (uint32_t)(row * ROWB + c16 * 16);                   \
            size_t ao = (q0 + (size_t)row) * KTOT + kofs_ + c16 * 8;          \
            cp_async16(stg_ + d,       g_A + ao);                             \
            size_t bo = (n0 + (size_t)row) * KTOT + kofs_ + c16 * 8;          \
            cp_async16(stg_ + ARR + d, g_B + bo);                             \
        }                                                                     \
        CP_COMMIT();                                                          \
    } while (0)

    LOAD_STAGE(0, 0);
    int lr = lane & 15, lc = (lane >> 4) * 8;

    for (int kc = 0; kc < 8; kc++) {
        if (kc < 7) { LOAD_STAGE(kc + 1, (kc + 1) & 1); CP_WAIT1(); }
        else        { CP_WAIT0(); }
        __syncthreads();
        uint32_t stg = sb + (kc & 1) * STG;
#pragma unroll
        for (int ks = 0; ks < 2; ks++) {
            uint32_t coff = (uint32_t)((ks * 16 + lc) * 2);
            uint32_t bg[8];
#pragma unroll
            for (int h = 0; h < 2; h++) {
                uint32_t bd = stg + ARR + (uint32_t)((wn * 32 + h * 16 + lr) * ROWB) + coff;
                ldsm4(bg[h * 4 + 0], bg[h * 4 + 1], bg[h * 4 + 2], bg[h * 4 + 3], bd);
            }
#pragma unroll
            for (int mi = 0; mi < 4; mi++) {
                uint32_t ad = stg + (uint32_t)((wm * 64 + mi * 16 + lr) * ROWB) + coff;
                uint32_t a0, a1, a2, a3;
                ldsm4(a0, a1, a2, a3, ad);
#pragma unroll
                for (int ni = 0; ni < 4; ni++) {
                    int h = ni >> 1, s2 = ni & 1;
                    mma_fp(acc[mi][ni], a0, a1, a2, a3, bg[h * 4 + s2], bg[h * 4 + s2 + 2]);
                }
            }
        }
        __syncthreads();
    }

    int g = lane >> 2, tc = lane & 3;
#pragma unroll
    for (int mi = 0; mi < 4; mi++) {
        size_t r0 = q0 + (size_t)(wm * 64 + mi * 16 + g);
        size_t r1 = r0 + 8;
#pragma unroll
        for (int ni = 0; ni < 4; ni++) {
            size_t col = n0 + (size_t)(wn * 32 + ni * 8 + tc * 2);
            *(float2*)(out + r0 * NKEYS + col) = make_float2(acc[mi][ni][0], acc[mi][ni][1]);
            *(float2*)(out + r1 * NKEYS + col) = make_float2(acc[mi][ni][2], acc[mi][ni][3]);
        }
    }
}

extern "C" void kernel_launch(void* const* d_in, const int* in_sizes, int n_in,
                              void* d_out, int out_size) {
    const float* query    = (const float*)d_in[0];
    const float* keys     = (const float*)d_in[1];
    const float* codebook = (const float*)d_in[2];
    const float* S        = (const float*)d_in[3];
    float* out = (float*)d_out;

    prep1_kernel<<<NKEYS / 8, 256>>>(keys, codebook, S);

    build_A_kernel<<<QDIM, 128>>>(query);

    int shP = 3 * PARR;  // 104448
    cudaFuncSetAttribute(proj_kernel, cudaFuncAttributeMaxDynamicSharedMemorySize, shP);
    proj_kernel<<<NKEYS / 128, 256, shP>>>();

    fixup_kernel<<<256, 256>>>(keys, codebook, S);

    int shG = 2 * STG;   // 40960
    cudaFuncSetAttribute(gemm_kernel, cudaFuncAttributeMaxDynamicSharedMemorySize, shG);
    dim3 grid(QDIM / 128, NKEYS / 128);
    gemm_kernel<<<grid, 256, shG>>>(out);
}

// round 17
// speedup vs baseline: 2.0823x; 1.0185x over previous
#include <cuda_runtime.h>
#include <cuda_bf16.h>
#include <cuda_fp16.h>
#include <math.h>
#include <stdint.h>

#define NKEYS 131072
#define DDIM 128
#define QDIM 512
#define KTOT 256
#define MAXQ 262144
#define SIGN_TH 2.2e-3f

__device__ __half        g_B [(size_t)NKEYS * KTOT];   // [vn*x_mse | coef*sign] fp16
__device__ __half        g_R [(size_t)NKEYS * DDIM];   // residual fp16
__device__ float         g_C [(size_t)NKEYS];
__device__ float         g_Rn[(size_t)NKEYS];
__device__ float         g_Vn[(size_t)NKEYS];
__device__ __half        g_Sh[DDIM * DDIM];            // S fp16
__device__ float         g_St[DDIM * DDIM];            // S^T fp32
__device__ __half        g_A [(size_t)QDIM * KTOT];    // [q | Sq] fp16
__device__ int           g_qcount;
__device__ uint32_t      g_queue[MAXQ];

__device__ __forceinline__ uint32_t smem_u32(const void* p) {
    uint32_t a;
    asm("{ .reg .u64 t; cvta.to.shared.u64 t, %1; cvt.u32.u64 %0, t; }" : "=r"(a) : "l"(p));
    return a;
}
__device__ __forceinline__ void cp_async16(uint32_t dst, const void* src) {
    uint64_t g;
    asm("cvta.to.global.u64 %0, %1;" : "=l"(g) : "l"(src));
    asm volatile("cp.async.cg.shared.global [%0], [%1], 16;" :: "r"(dst), "l"(g));
}
#define CP_COMMIT() asm volatile("cp.async.commit_group;" ::: "memory")
#define CP_WAIT(N)  asm volatile("cp.async.wait_group %0;" :: "n"(N) : "memory")

__device__ __forceinline__ void ldsm4(uint32_t& r0, uint32_t& r1, uint32_t& r2,
                                      uint32_t& r3, uint32_t addr) {
    asm volatile("ldmatrix.sync.aligned.m8n8.x4.shared.b16 {%0,%1,%2,%3}, [%4];"
                 : "=r"(r0), "=r"(r1), "=r"(r2), "=r"(r3) : "r"(addr));
}
__device__ __forceinline__ void mma_fp(float* c, uint32_t a0, uint32_t a1,
                                       uint32_t a2, uint32_t a3,
                                       uint32_t b0, uint32_t b1) {
    asm volatile(
        "mma.sync.aligned.m16n8k16.row.col.f32.f16.f16.f32 "
        "{%0,%1,%2,%3}, {%4,%5,%6,%7}, {%8,%9}, {%0,%1,%2,%3};"
        : "+f"(c[0]), "+f"(c[1]), "+f"(c[2]), "+f"(c[3])
        : "r"(a0), "r"(a1), "r"(a2), "r"(a3), "r"(b0), "r"(b1));
}
__device__ __forceinline__ uint32_t pack2h(__half a, __half b) {
    union { __half h[2]; uint32_t u; } t;
    t.h[0] = a; t.h[1] = b;
    return t.u;
}
__device__ __forceinline__ void enqueue(uint32_t n, uint32_t j) {
    uint32_t idx = (uint32_t)atomicAdd(&g_qcount, 1);
    if (idx < MAXQ) g_queue[idx] = (n << 7) | j;
}

// --- prep1: warp-per-key; blocks 0..63 also convert/transpose S; zero queue ---
__global__ __launch_bounds__(256) void prep1_kernel(const float* __restrict__ keys,
                                                    const float* __restrict__ cb,
                                                    const float* __restrict__ S) {
    int tid = threadIdx.x;
    if (blockIdx.x < 64) {
        int i = blockIdx.x * 256 + tid;
        float sv = S[i];
        g_Sh[i] = __float2half(sv);
        int j = i >> 7, ii = i & 127;
        g_St[ii * 128 + j] = sv;
        if (i == 0) g_qcount = 0;
    }
    int lane = tid & 31, w = tid >> 5;
    size_t n = (size_t)blockIdx.x * 8 + w;
    float c0 = cb[0], c1 = cb[1], c2 = cb[2], c3 = cb[3];
    float m01 = 0.5f * (c0 + c1), m12 = 0.5f * (c1 + c2), m23 = 0.5f * (c2 + c3);

    float4 kv = *(const float4*)(keys + n * DDIM + lane * 4);
    float ss = kv.x * kv.x + kv.y * kv.y + kv.z * kv.z + kv.w * kv.w;
#pragma unroll
    for (int o = 16; o; o >>= 1) ss += __shfl_xor_sync(0xffffffffu, ss, o);
    float vn = sqrtf(ss);
    float inv = 1.f / (vn + 1e-8f);

    float x[4] = {kv.x * inv, kv.y * inv, kv.z * inv, kv.w * inv};
    float r[4], rr = 0.f;
    __half bq[4], rq[4];
#pragma unroll
    for (int i = 0; i < 4; i++) {
        float xm = (x[i] >= m12) ? ((x[i] >= m23) ? c3 : c2)
                                 : ((x[i] >= m01) ? c1 : c0);
        r[i] = x[i] - xm;
        rr += r[i] * r[i];
        bq[i] = __float2half(vn * xm);
        rq[i] = __float2half(r[i]);
    }
    *(uint2*)&g_B[n * KTOT + lane * 4] = make_uint2(pack2h(bq[0], bq[1]), pack2h(bq[2], bq[3]));
    *(uint2*)&g_R[n * DDIM + lane * 4] = make_uint2(pack2h(rq[0], rq[1]), pack2h(rq[2], rq[3]));

#pragma unroll
    for (int o = 16; o; o >>= 1) rr += __shfl_xor_sync(0xffffffffu, rr, o);
    float rn = sqrtf(rr);
    if (lane == 0) {
        g_C[n]  = vn * rn * 0.009797554543986288f;  // sqrt(pi/2)/128
        g_Rn[n] = rn;
        g_Vn[n] = vn;
    }
}

// --- build_A: 512 blocks, 1 query each; coalesced reads of transposed S ---
__global__ __launch_bounds__(128) void build_A_kernel(const float* __restrict__ query) {
    __shared__ float qsh[128];
    int q = blockIdx.x, j = threadIdx.x;
    float qv = query[q * DDIM + j];
    qsh[j] = qv;
    __syncthreads();
    float acc = 0.f;
#pragma unroll 16
    for (int i = 0; i < 128; i++) acc += qsh[i] * g_St[i * 128 + j];
    g_A[(size_t)q * KTOT + j] = __float2half(qv);
    g_A[(size_t)q * KTOT + 128 + j] = __float2half(acc);
}

// --- proj: sign(R @ S^T)*coef -> g_B[:,128:256]; fp16 1-term; occ 2 ---
#define PROW 272
#define PARR 34816

__global__ __launch_bounds__(256, 2) void proj_kernel() {
    extern __shared__ __align__(16) char sm[];
    uint32_t sb = smem_u32(sm);
    int tid = threadIdx.x, wid = tid >> 5, lane = tid & 31;
    int wm = wid >> 2, wn = wid & 3;
    size_t n0 = (size_t)blockIdx.x * 128;

#pragma unroll
    for (int it = 0; it < 8; it++) {
        int idx = tid + it * 256;
        int row = idx >> 4, c16 = idx & 15;
        uint32_t d = (uint32_t)(row * PROW + c16 * 16);
        cp_async16(sb + d,        g_R + (n0 + (size_t)row) * DDIM + c16 * 8);
        cp_async16(sb + PARR + d, g_Sh + (size_t)row * DDIM + c16 * 8);
    }
    CP_COMMIT();

    float acc[4][4][4];
#pragma unroll
    for (int i = 0; i < 4; i++)
#pragma unroll
        for (int j = 0; j < 4; j++)
#pragma unroll
            for (int k = 0; k < 4; k++) acc[i][j][k] = 0.f;

    CP_WAIT(0);
    __syncthreads();

    int lr = lane & 15, lc = (lane >> 4) * 8;
#pragma unroll
    for (int ks = 0; ks < 8; ks++) {
        uint32_t coff = (uint32_t)((ks * 16 + lc) * 2);
        uint32_t bh[8];
#pragma unroll
        for (int h = 0; h < 2; h++) {
            uint32_t bd = sb + PARR + (uint32_t)((wn * 32 + h * 16 + lr) * PROW) + coff;
            ldsm4(bh[h * 4 + 0], bh[h * 4 + 1], bh[h * 4 + 2], bh[h * 4 + 3], bd);
        }
#pragma unroll
        for (int mi = 0; mi < 4; mi++) {
            uint32_t ad = sb + (uint32_t)((wm * 64 + mi * 16 + lr) * PROW) + coff;
            uint32_t a0, a1, a2, a3;
            ldsm4(a0, a1, a2, a3, ad);
#pragma unroll
            for (int ni = 0; ni < 4; ni++) {
                int h = ni >> 1, s2 = ni & 1;
                mma_fp(acc[mi][ni], a0, a1, a2, a3, bh[h * 4 + s2], bh[h * 4 + s2 + 2]);
            }
        }
    }

    int g = lane >> 2, tc = lane & 3;
#pragma unroll
    for (int mi = 0; mi < 4; mi++) {
        size_t r0 = n0 + (size_t)(wm * 64 + mi * 16 + g);
        size_t r1 = r0 + 8;
        float tA = g_Rn[r0] * SIGN_TH, tB = g_Rn[r1] * SIGN_TH;
        __half cA = __float2half(g_C[r0]), cB = __float2half(g_C[r1]);
#pragma unroll
        for (int ni = 0; ni < 4; ni++) {
            int j0 = wn * 32 + ni * 8 + tc * 2;
            bool p0 = acc[mi][ni][0] >= 0.f, p1 = acc[mi][ni][1] >= 0.f;
            bool p2 = acc[mi][ni][2] >= 0.f, p3 = acc[mi][ni][3] >= 0.f;
            *(uint32_t*)&g_B[r0 * KTOT + 128 + j0] =
                pack2h(p0 ? cA : __hneg(cA), p1 ? cA : __hneg(cA));
            *(uint32_t*)&g_B[r1 * KTOT + 128 + j0] =
                pack2h(p2 ? cB : __hneg(cB), p3 ? cB : __hneg(cB));
            if (fabsf(acc[mi][ni][0]) < tA) enqueue((uint32_t)r0, (uint32_t)j0);
            if (fabsf(acc[mi][ni][1]) < tA) enqueue((uint32_t)r0, (uint32_t)(j0 + 1));
            if (fabsf(acc[mi][ni][2]) < tB) enqueue((uint32_t)r1, (uint32_t)j0);
            if (fabsf(acc[mi][ni][3]) < tB) enqueue((uint32_t)r1, (uint32_t)(j0 + 1));
        }
    }
}

// --- fixup: recompute ambiguous signs in exact fp32 (vn preloaded) ---
__global__ __launch_bounds__(256) void fixup_kernel(const float* __restrict__ keys,
                                                    const float* __restrict__ cb,
                                                    const float* __restrict__ S) {
    int lane = threadIdx.x & 31;
    int w = (blockIdx.x * blockDim.x + threadIdx.x) >> 5;
    int nw = (gridDim.x * blockDim.x) >> 5;
    int cnt = g_qcount;
    if (cnt > MAXQ) cnt = MAXQ;
    float c0 = cb[0], c1 = cb[1], c2 = cb[2], c3 = cb[3];
    float m01 = 0.5f * (c0 + c1), m12 = 0.5f * (c1 + c2), m23 = 0.5f * (c2 + c3);

    for (int e = w; e < cnt; e += nw) {
        uint32_t pk = g_queue[e];
        size_t n = (size_t)(pk >> 7);
        uint32_t j = pk & 127u;
        float4 kv = *(const float4*)(keys + n * DDIM + lane * 4);
        float4 sv = *(const float4*)(S + (size_t)j * DDIM + lane * 4);
        float vn = g_Vn[n];
        float inv = 1.f / (vn + 1e-8f);
        float x[4] = {kv.x * inv, kv.y * inv, kv.z * inv, kv.w * inv};
        float svv[4] = {sv.x, sv.y, sv.z, sv.w};
        float dot = 0.f;
#pragma unroll
        for (int i = 0; i < 4; i++) {
            float xm = (x[i] >= m12) ? ((x[i] >= m23) ? c3 : c2)
                                     : ((x[i] >= m01) ? c1 : c0);
            dot += (x[i] - xm) * svv[i];
        }
#pragma unroll
        for (int o = 16; o; o >>= 1) dot += __shfl_xor_sync(0xffffffffu, dot, o);
        if (lane == 0) {
            float coef = g_C[n];
            g_B[n * KTOT + 128 + j] = __float2half((dot >= 0.f) ? coef : -coef);
        }
    }
}

// --- main GEMM: fp16, 1 term (A.B), K=256, 3-stage pipeline, occ 2 ---
#define ROWB 80
#define ARR  10240
#define STG  20480    // 2*ARR

__global__ __launch_bounds__(256, 2) void gemm_kernel(float* __restrict__ out) {
    extern __shared__ __align__(16) char sm[];
    uint32_t sb = smem_u32(sm);
    int tid = threadIdx.x, wid = tid >> 5, lane = tid & 31;
    int wm = wid >> 2, wn = wid & 3;
    size_t q0 = (size_t)blockIdx.x * 128;
    size_t n0 = (size_t)blockIdx.y * 128;

    float acc[4][4][4];
#pragma unroll
    for (int i = 0; i < 4; i++)
#pragma unroll
        for (int j = 0; j < 4; j++)
#pragma unroll
            for (int k = 0; k < 4; k++) acc[i][j][k] = 0.f;

#define LOAD_STAGE(KC, S_)                                                    \
    do {                                                                      \
        uint32_t stg_ = sb + (S_) * STG;                                      \
        int kofs_ = (KC) * 32;                                                \
        _Pragma("unroll")                                                     \
        for (int it = 0; it < 2; it++) {                                      \
            int idx = tid + it * 256;                                         \
            int row = idx >> 2, c16 = idx & 3;                                \
            uint32_t d = (uint32_t)(row * ROWB + c16 * 16);                   \
            size_t ao = (q0 + (size_t)row) * KTOT + kofs_ + c16 * 8;          \
            cp_async16(stg_ + d,       g_A + ao);                             \
            size_t bo = (n0 + (size_t)row) * KTOT + kofs_ + c16 * 8;          \
            cp_async16(stg_ + ARR + d, g_B + bo);                             \
        }                                                                     \
        CP_COMMIT();                                                          \
    } while (0)

    LOAD_STAGE(0, 0);
    LOAD_STAGE(1, 1);
    int lr = lane & 15, lc = (lane >> 4) * 8;

    for (int kc = 0; kc < 8; kc++) {
        if (kc < 6) { LOAD_STAGE(kc + 2, (kc + 2) % 3); CP_WAIT(2); }
        else if (kc == 6) { CP_WAIT(1); }
        else { CP_WAIT(0); }
        __syncthreads();
        uint32_t stg = sb + (kc % 3) * STG;
#pragma unroll
        for (int ks = 0; ks < 2; ks++) {
            uint32_t coff = (uint32_t)((ks * 16 + lc) * 2);
            uint32_t bg[8];
#pragma unroll
            for (int h = 0; h < 2; h++) {
                uint32_t bd = stg + ARR + (uint32_t)((wn * 32 + h * 16 + lr) * ROWB) + coff;
                ldsm4(bg[h * 4 + 0], bg[h * 4 + 1], bg[h * 4 + 2], bg[h * 4 + 3], bd);
            }
#pragma unroll
            for (int mi = 0; mi < 4; mi++) {
                uint32_t ad = stg + (uint32_t)((wm * 64 + mi * 16 + lr) * ROWB) + coff;
                uint32_t a0, a1, a2, a3;
                ldsm4(a0, a1, a2, a3, ad);
#pragma unroll
                for (int ni = 0; ni < 4; ni++) {
                    int h = ni >> 1, s2 = ni & 1;
                    mma_fp(acc[mi][ni], a0, a1, a2, a3, bg[h * 4 + s2], bg[h * 4 + s2 + 2]);
                }
            }
        }
        __syncthreads();
    }

    int g = lane >> 2, tc = lane & 3;
#pragma unroll
    for (int mi = 0; mi < 4; mi++) {
        size_t r0 = q0 + (size_t)(wm * 64 + mi * 16 + g);
        size_t r1 = r0 + 8;
#pragma unroll
        for (int ni = 0; ni < 4; ni++) {
            size_t col = n0 + (size_t)(wn * 32 + ni * 8 + tc * 2);
            *(float2*)(out + r0 * NKEYS + col) = make_float2(acc[mi][ni][0], acc[mi][ni][1]);
            *(float2*)(out + r1 * NKEYS + col) = make_float2(acc[mi][ni][2], acc[mi][ni][3]);
        }
    }
}

extern "C" void kernel_launch(void* const* d_in, const int* in_sizes, int n_in,
                              void* d_out, int out_size) {
    const float* query    = (const float*)d_in[0];
    const float* keys     = (const float*)d_in[1];
    const float* codebook = (const float*)d_in[2];
    const float* S        = (const float*)d_in[3];
    float* out = (float*)d_out;

    prep1_kernel<<<NKEYS / 8, 256>>>(keys, codebook, S);

    build_A_kernel<<<QDIM, 128>>>(query);

    int shP = 2 * PARR;  // 69632
    cudaFuncSetAttribute(proj_kernel, cudaFuncAttributeMaxDynamicSharedMemorySize, shP);
    proj_kernel<<<NKEYS / 128, 256, shP>>>();

    fixup_kernel<<<1024, 256>>>(keys, codebook, S);

    int shG = 3 * STG;   // 61440
    cudaFuncSetAttribute(gemm_kernel, cudaFuncAttributeMaxDynamicSharedMemorySize, shG);
    dim3 grid(QDIM / 128, NKEYS / 128);
    gemm_kernel<<<grid, 256, shG>>>(out);
}